// round 10
// baseline (speedup 1.0000x reference)
#include <cuda_runtime.h>
#include <cuda_fp16.h>
#include <cstdint>

#define NN   20000
#define EG   200000
#define ELG  400000
#define HD   256
#define HD2  512
#define NL   4
#define NG   128
#define KSB  80   // padded smem row stride in BYTES (64B payload + 16 pad), ldmatrix conflict-free

// ---------------- scratch (device globals; no allocations allowed) ----------------
__device__ float  g_P[NN * HD];
__device__ float  g_Q[NN * HD];
__device__ float  g_h[EG * HD];        // current layer state (pre-BN)
__device__ float4 g_nbg[EG];
__device__ float4 g_ebg[ELG];
__device__ int    g_counts_lg[EG];
__device__ int    g_counts_g[NN];
__device__ int    g_rowptr_lg[EG + 1];
__device__ int    g_rowptr_g[NN + 1];
__device__ int    g_cursor_lg[EG];
__device__ int    g_cursor_g[NN];
__device__ int    g_src_sorted[ELG];
__device__ float4 g_nbg_sorted[ELG];
__device__ float4 g_ebg_sorted[ELG];
__device__ int    g_eid_sorted[EG];
__device__ double g_bnsum[HD];
__device__ double g_bnsq[HD];
__device__ float  g_bnscale[HD];
__device__ float  g_bnshift[HD];
__device__ float  g_gsum[NG * HD];
__device__ int    g_cnt[NG];
__device__ int    g_blksum[256];

// fp16 hi/lo A operands (padded +128 rows; device globals are zero-initialized)
__device__ __half g_hnh[(NN + 128) * HD];
__device__ __half g_hnl[(NN + 128) * HD];
__device__ __half g_hmh[(EG + 128) * HD];
__device__ __half g_hml[(EG + 128) * HD];
__device__ __half g_m2h[(EG + 128) * HD2];
__device__ __half g_m2l[(EG + 128) * HD2];

// weights single fp16, [N,K] K-contiguous
#define WOFF_P  0
#define WOFF_Q  65536
#define WOFF_W1 131072              // + l*131072
#define WOFF_W2 655360              // + l*131072
#define WTOT    1179648
__device__ __half g_Wv[WTOT];

// ---------------- mma / cp.async helpers (sm_80+ PTX, valid on sm_100 base) ----------------
__device__ __forceinline__ void ldsm4(uint32_t addr, uint32_t* r) {
    asm volatile("ldmatrix.sync.aligned.m8n8.x4.shared.b16 {%0,%1,%2,%3}, [%4];"
                 : "=r"(r[0]), "=r"(r[1]), "=r"(r[2]), "=r"(r[3]) : "r"(addr));
}
__device__ __forceinline__ void mma_f16(float* c, const uint32_t* a, uint32_t b0, uint32_t b1) {
    asm volatile("mma.sync.aligned.m16n8k16.row.col.f32.f16.f16.f32 "
                 "{%0,%1,%2,%3}, {%4,%5,%6,%7}, {%8,%9}, {%0,%1,%2,%3};"
                 : "+f"(c[0]), "+f"(c[1]), "+f"(c[2]), "+f"(c[3])
                 : "r"(a[0]), "r"(a[1]), "r"(a[2]), "r"(a[3]), "r"(b0), "r"(b1));
}
__device__ __forceinline__ uint32_t smem_u32(const void* p) {
    uint32_t a;
    asm("{ .reg .u64 t; cvta.to.shared.u64 t, %1; cvt.u32.u64 %0, t; }" : "=r"(a) : "l"(p));
    return a;
}
__device__ __forceinline__ void cpa16(uint32_t s, const void* g) {
    asm volatile("cp.async.cg.shared.global [%0], [%1], 16;" :: "r"(s), "l"(g));
}
#define CP_COMMIT() asm volatile("cp.async.commit_group;" ::: "memory")
#define CP_WAIT1()  asm volatile("cp.async.wait_group 1;" ::: "memory")

// fp16 hi/lo split
__device__ __forceinline__ void split16(float x, __half& h, __half& l) {
    h = __float2half(x);
    l = __float2half(x - __half2float(h));
}

// smem stage layout (bytes): A_hi | A_lo | B, each 128*KSB = 10240
#define SA_HI 0
#define SA_LO 10240
#define SB_V  20480
#define STG   30720
#define NSTG  3
#define MG_SMEM (NSTG * STG)

// ---------------- fp16 2-pass mma GEMM: C[M,N] = A[M,K] @ B[K,N] (+bias, relu, res) ----------
// grid: x = N-tile (fast-varying -> consecutive CTAs share the A tile in L2), y = M-tile.
__global__ void __launch_bounds__(256, 1) k_mgemm(
    const float* __restrict__ bias,
    int M, int N, int K, int relu, int abuf, int cbuf, int addres, size_t woff)
{
    extern __shared__ char dsm[];
    const __half* Ah_ = (abuf == 0) ? g_hnh : (abuf == 1) ? g_hmh : g_m2h;
    const __half* Al_ = (abuf == 0) ? g_hnl : (abuf == 1) ? g_hml : g_m2l;
    const __half* Bv_ = g_Wv + woff;

    int tid = threadIdx.x, wid = tid >> 5, lid = tid & 31;
    int bm = blockIdx.y * 128;
    int bn = blockIdx.x * 128;
    int wm = (wid >> 2) * 64;
    int wn = (wid & 3) * 32;

    // cp.async: 4 threads/row cover 64 bytes (32 fp16); rows r0 and r0+64
    int r0 = tid >> 2, e0 = (tid & 3) * 8;       // element offset within chunk
    int r1 = r0 + 64;
    const __half* Ah0 = Ah_ + (size_t)(bm + r0) * K + e0;
    const __half* Ah1 = Ah_ + (size_t)(bm + r1) * K + e0;
    const __half* Al0 = Al_ + (size_t)(bm + r0) * K + e0;
    const __half* Al1 = Al_ + (size_t)(bm + r1) * K + e0;
    const __half* Bv0 = Bv_ + (size_t)(bn + r0) * K + e0;
    const __half* Bv1 = Bv_ + (size_t)(bn + r1) * K + e0;
    uint32_t d0 = (uint32_t)(r0 * KSB + e0 * 2);
    uint32_t d1 = (uint32_t)(r1 * KSB + e0 * 2);

    uint32_t sbase = smem_u32(dsm);

    // ldmatrix per-lane offsets (bytes)
    int a_ml = (lid & 7) + ((lid >> 3) & 1) * 8;
    int a_kb = (lid >> 4) * 16;
    int b_nl = (lid & 7) + (lid >> 4) * 8;
    int b_kb = ((lid >> 3) & 1) * 16;
    uint32_t aoff[4], boffm[2];
    #pragma unroll
    for (int mt = 0; mt < 4; mt++)
        aoff[mt] = (uint32_t)((wm + mt * 16 + a_ml) * KSB + a_kb);
    #pragma unroll
    for (int p = 0; p < 2; p++)
        boffm[p] = (uint32_t)((wn + p * 16 + b_nl) * KSB + b_kb);

    float acc[4][4][4];
    #pragma unroll
    for (int i = 0; i < 4; i++)
        #pragma unroll
        for (int j = 0; j < 4; j++)
            #pragma unroll
            for (int q = 0; q < 4; q++) acc[i][j][q] = 0.f;

    int nck = K >> 5;   // chunks of 32 fp16 (64 bytes/row)

    auto load_stage = [&](int s, int c) {
        uint32_t sb = sbase + s * STG;
        int co = c * 32;
        cpa16(sb + SA_HI + d0, Ah0 + co); cpa16(sb + SA_HI + d1, Ah1 + co);
        cpa16(sb + SA_LO + d0, Al0 + co); cpa16(sb + SA_LO + d1, Al1 + co);
        cpa16(sb + SB_V  + d0, Bv0 + co); cpa16(sb + SB_V  + d1, Bv1 + co);
    };

    load_stage(0, 0); CP_COMMIT();
    load_stage(1, 1); CP_COMMIT();

    for (int c = 0; c < nck; c++) {
        CP_WAIT1();
        __syncthreads();
        if (c + 2 < nck) load_stage((c + 2) % NSTG, c + 2);
        CP_COMMIT();
        uint32_t stb = sbase + (c % NSTG) * STG;
        #pragma unroll
        for (int kk = 0; kk < 2; kk++) {
            uint32_t ko = kk * 32;   // 32 bytes = k16 fp16 per mma
            uint32_t ah[4][4], al[4][4], bv[2][4];
            #pragma unroll
            for (int mt = 0; mt < 4; mt++) {
                ldsm4(stb + SA_HI + aoff[mt] + ko, ah[mt]);
                ldsm4(stb + SA_LO + aoff[mt] + ko, al[mt]);
            }
            #pragma unroll
            for (int p = 0; p < 2; p++)
                ldsm4(stb + SB_V + boffm[p] + ko, bv[p]);
            #pragma unroll
            for (int mt = 0; mt < 4; mt++) {
                #pragma unroll
                for (int nt = 0; nt < 4; nt++) {
                    int p = nt >> 1, o = (nt & 1) * 2;
                    mma_f16(acc[mt][nt], ah[mt], bv[p][o], bv[p][o + 1]);   // Ah*B
                    mma_f16(acc[mt][nt], al[mt], bv[p][o], bv[p][o + 1]);   // Al*B
                }
            }
        }
        __syncthreads();
    }

    // ---- epilogue ----
    int l4 = lid >> 2, lc = (lid & 3) * 2;
    #pragma unroll
    for (int mt = 0; mt < 4; mt++) {
        #pragma unroll
        for (int nt = 0; nt < 4; nt++) {
            int m = bm + wm + mt * 16 + l4;
            int n = bn + wn + nt * 8 + lc;
            float2 bia = make_float2(0.f, 0.f);
            if (bias) bia = *(const float2*)&bias[n];
            #pragma unroll
            for (int half_ = 0; half_ < 2; half_++) {
                int mm = m + half_ * 8;
                if (mm < M) {
                    float v0 = acc[mt][nt][half_ * 2 + 0] + bia.x;
                    float v1 = acc[mt][nt][half_ * 2 + 1] + bia.y;
                    if (relu) { v0 = fmaxf(v0, 0.f); v1 = fmaxf(v1, 0.f); }
                    if (cbuf == 2) {
                        // fp16 hi/lo split store to mid2
                        __half h0, l0, h1, l1;
                        split16(v0, h0, l0);
                        split16(v1, h1, l1);
                        __half2 ph; ph.x = h0; ph.y = h1;
                        __half2 pl; pl.x = l0; pl.y = l1;
                        *(__half2*)&g_m2h[(size_t)mm * N + n] = ph;
                        *(__half2*)&g_m2l[(size_t)mm * N + n] = pl;
                    } else {
                        float* C = (cbuf == 0) ? g_P : (cbuf == 1) ? g_Q : g_h;
                        if (addres) {
                            float2 rr = *(const float2*)&g_h[(size_t)mm * N + n];
                            v0 += rr.x; v1 += rr.y;
                        }
                        float2 ov; ov.x = v0; ov.y = v1;
                        *(float2*)&C[(size_t)mm * N + n] = ov;
                    }
                }
            }
        }
    }
}

// ---------------- weight convert: in[K,N] fp32 -> [N,K] fp16 ----------------
__global__ void k_wconv(const float* __restrict__ in, int K, int N, size_t woff) {
    int wid = threadIdx.x >> 5, lane = threadIdx.x & 31;
    int n = blockIdx.x * 8 + wid;
    if (n >= N) return;
    for (int k = lane; k < K; k += 32)
        g_Wv[woff + (size_t)n * K + k] = __float2half(in[(size_t)k * N + n]);
}

// ---------------- setup / zero ----------------
__global__ void k_zero_setup() {
    int i = blockIdx.x * 256 + threadIdx.x;
    if (i < EG)       g_counts_lg[i] = 0;
    if (i < NN)       g_counts_g[i] = 0;
    if (i < NG * HD)  g_gsum[i] = 0.f;
    if (i < NG)       g_cnt[i] = 0;
}

__global__ void k_zero_bn() {
    int f = threadIdx.x;
    g_bnsum[f] = 0.0;
    g_bnsq[f] = 0.0;
}

// ---------------- histograms ----------------
__global__ void k_hist_lg(const int* __restrict__ eilg) {
    int e = blockIdx.x * 256 + threadIdx.x;
    if (e < ELG) atomicAdd(&g_counts_lg[eilg[ELG + e]], 1);
}
__global__ void k_hist_g(const int* __restrict__ eig) {
    int e = blockIdx.x * 256 + threadIdx.x;
    if (e < EG) atomicAdd(&g_counts_g[eig[EG + e]], 1);
}
__global__ void k_hist_batch(const int* __restrict__ bv) {
    int n = blockIdx.x * 256 + threadIdx.x;
    if (n < NN) atomicAdd(&g_cnt[bv[n]], 1);
}

// ---------------- parallel 3-phase exclusive scan ----------------
// phase 1: per-block sums
__global__ void k_scan1(int which) {
    const int* in = (which == 0) ? g_counts_lg : g_counts_g;
    int n = (which == 0) ? EG : NN;
    int b = blockIdx.x, t = threadIdx.x, lane = t & 31, w = t >> 5;
    __shared__ int ws[32];
    int i = b * 1024 + t;
    int v = (i < n) ? in[i] : 0;
    #pragma unroll
    for (int o = 16; o > 0; o >>= 1) v += __shfl_xor_sync(0xFFFFFFFF, v, o);
    if (lane == 0) ws[w] = v;
    __syncthreads();
    if (t == 0) {
        int s = 0;
        #pragma unroll
        for (int k = 0; k < 32; k++) s += ws[k];
        g_blksum[b] = s;
    }
}
// phase 2: exclusive scan of block sums (nb <= 256), single block 256 threads
__global__ void k_scan2(int nb) {
    __shared__ int ws[8];
    int t = threadIdx.x, lane = t & 31, w = t >> 5;
    int v = (t < nb) ? g_blksum[t] : 0;
    int x = v;
    #pragma unroll
    for (int o = 1; o < 32; o <<= 1) {
        int y = __shfl_up_sync(0xFFFFFFFF, x, o);
        if (lane >= o) x += y;
    }
    if (lane == 31) ws[w] = x;
    __syncthreads();
    if (w == 0 && lane < 8) {
        int s = ws[lane];
        #pragma unroll
        for (int o = 1; o < 8; o <<= 1) {
            int y = __shfl_up_sync(0xFF, s, o);
            if (lane >= o) s += y;
        }
        ws[lane] = s;
    }
    __syncthreads();
    int woff = (w > 0) ? ws[w - 1] : 0;
    if (t < nb) g_blksum[t] = woff + x - v;   // exclusive
}
// phase 3: block-local exclusive scan + block offset
__global__ void k_scan3(int which) {
    const int* in;
    int* out;
    int n;
    if (which == 0) { in = g_counts_lg; out = g_rowptr_lg; n = EG; }
    else            { in = g_counts_g;  out = g_rowptr_g;  n = NN; }
    __shared__ int ws[32];
    int b = blockIdx.x, t = threadIdx.x, lane = t & 31, w = t >> 5;
    int i = b * 1024 + t;
    int v = (i < n) ? in[i] : 0;
    int x = v;
    #pragma unroll
    for (int o = 1; o < 32; o <<= 1) {
        int y = __shfl_up_sync(0xFFFFFFFF, x, o);
        if (lane >= o) x += y;
    }
    if (lane == 31) ws[w] = x;
    __syncthreads();
    if (w == 0) {
        int s = ws[lane];
        #pragma unroll
        for (int o = 1; o < 32; o <<= 1) {
            int y = __shfl_up_sync(0xFFFFFFFF, s, o);
            if (lane >= o) s += y;
        }
        ws[lane] = s;
    }
    __syncthreads();
    int woff = (w > 0) ? ws[w - 1] : 0;
    int base = g_blksum[b];
    if (i < n) out[i] = base + woff + x - v;
    if (i == n - 1) out[n] = base + woff + x;   // total
}

__global__ void k_prepcur() {
    int i = blockIdx.x * 256 + threadIdx.x;
    if (i < EG) g_cursor_lg[i] = g_rowptr_lg[i];
    if (i < NN) g_cursor_g[i] = g_rowptr_g[i];
}

// ---------------- tiny 4->4 basis projections ----------------
__global__ void k_basis(const float* __restrict__ in, const float* __restrict__ W,
                        const float* __restrict__ b, int which) {
    int R = (which == 0) ? EG : ELG;
    float4* out = (which == 0) ? g_nbg : g_ebg;
    int r = blockIdx.x * 256 + threadIdx.x;
    if (r >= R) return;
    float4 v = ((const float4*)in)[r];
    float4 o;
    o.x = v.x * W[0] + v.y * W[4] + v.z * W[8]  + v.w * W[12] + b[0];
    o.y = v.x * W[1] + v.y * W[5] + v.z * W[9]  + v.w * W[13] + b[1];
    o.z = v.x * W[2] + v.y * W[6] + v.z * W[10] + v.w * W[14] + b[2];
    o.w = v.x * W[3] + v.y * W[7] + v.z * W[11] + v.w * W[15] + b[3];
    out[r] = o;
}

// ---------------- scatter (counting-sort finish) ----------------
__global__ void k_scatter_lg(const int* __restrict__ eilg) {
    int e = blockIdx.x * 256 + threadIdx.x;
    if (e >= ELG) return;
    int s = eilg[e];
    int d = eilg[ELG + e];
    int pos = atomicAdd(&g_cursor_lg[d], 1);
    g_src_sorted[pos] = s;
    g_nbg_sorted[pos] = g_nbg[s];
    g_ebg_sorted[pos] = g_ebg[e];
}
__global__ void k_scatter_g(const int* __restrict__ eig) {
    int e = blockIdx.x * 256 + threadIdx.x;
    if (e >= EG) return;
    int d = eig[EG + e];
    int pos = atomicAdd(&g_cursor_g[d], 1);
    g_eid_sorted[pos] = e;
}

// ---------------- node encoder: h_node = x_g @ W_enc + b_enc (fp16 hi/lo out) ----------------
__global__ void __launch_bounds__(256) k_enc(const float* __restrict__ xg,
                                             const float* __restrict__ Wenc,
                                             const float* __restrict__ benc) {
    __shared__ float xs[8][16];
    int t = threadIdx.x;
    int r0 = blockIdx.x * 8;
    if (t < 128) xs[t >> 4][t & 15] = xg[(r0 + (t >> 4)) * 16 + (t & 15)];
    __syncthreads();
    int f = t;
    float w[16];
    #pragma unroll
    for (int k = 0; k < 16; k++) w[k] = Wenc[k * HD + f];
    float b = benc[f];
    #pragma unroll
    for (int rr = 0; rr < 8; rr++) {
        float acc = b;
        #pragma unroll
        for (int k = 0; k < 16; k++) acc += xs[rr][k] * w[k];
        size_t idx = (size_t)(r0 + rr) * HD + f;
        __half h, l;
        split16(acc, h, l);
        g_hnh[idx] = h;
        g_hnl[idx] = l;
    }
}

// ---------------- first message embedding ----------------
__global__ void __launch_bounds__(256) k_h0(const float* __restrict__ ea,
                                            const float* __restrict__ xlg,
                                            const float* __restrict__ Wmsg,
                                            const float* __restrict__ bmsg,
                                            const int* __restrict__ eig) {
    __shared__ float sea[16][16];
    __shared__ float sxl[16][4];
    __shared__ int ssrc[16], sdst[16];
    int t = threadIdx.x;
    int e0 = blockIdx.x * 16;
    sea[t >> 4][t & 15] = ea[(size_t)e0 * 16 + t];
    if (t < 64) sxl[t >> 2][t & 3] = xlg[(size_t)e0 * 4 + t];
    if (t < 16) { ssrc[t] = eig[e0 + t]; sdst[t] = eig[EG + e0 + t]; }
    __syncthreads();
    int f = t;
    float wme[16];
    #pragma unroll
    for (int k = 0; k < 16; k++) wme[k] = Wmsg[(size_t)(512 + k) * HD + f];
    float wmx[4];
    #pragma unroll
    for (int k = 0; k < 4; k++) wmx[k] = Wmsg[(size_t)(528 + k) * HD + f];
    float bb = bmsg[f];
    #pragma unroll 1
    for (int ee = 0; ee < 16; ee++) {
        int e = e0 + ee;
        int s = ssrc[ee], d = sdst[ee];
        float acc = g_P[(size_t)s * HD + f] + g_Q[(size_t)d * HD + f] + bb;
        #pragma unroll
        for (int k = 0; k < 16; k++) acc += sea[ee][k] * wme[k];
        #pragma unroll
        for (int k = 0; k < 4; k++) acc += sxl[ee][k] * wmx[k];
        g_h[(size_t)e * HD + f] = acc;
    }
}

// ---------------- GENConv aggregation (online softmax, BN folded, fp16 hi/lo out) -------------
#define AGG_NPB 4
__global__ void __launch_bounds__(256) k_agg(const float* __restrict__ Wnb,
                                             const float* __restrict__ bnb,
                                             const float* __restrict__ Web,
                                             const float* __restrict__ beb,
                                             int use_bn) {
    int f = threadIdx.x;
    float w0 = Wnb[f], w1 = Wnb[HD + f], w2 = Wnb[2 * HD + f], w3 = Wnb[3 * HD + f];
    float e0 = Web[f], e1 = Web[HD + f], e2 = Web[2 * HD + f], e3 = Web[3 * HD + f];
    float cb = bnb[f] + beb[f];
    float sc = use_bn ? g_bnscale[f] : 1.f;
    float shv = use_bn ? g_bnshift[f] : 0.f;
    int d0 = blockIdx.x * AGG_NPB;
    const float NEG_INF = __int_as_float(0xff800000);
    #pragma unroll 1
    for (int dd = 0; dd < AGG_NPB; dd++) {
        int d = d0 + dd;
        int beg = g_rowptr_lg[d], end = g_rowptr_lg[d + 1];
        float xc = g_h[(size_t)d * HD + f];
        if (use_bn) xc = fmaxf(xc * sc + shv, 0.f);
        float M = NEG_INF, s = 0.f, w = 0.f;
        for (int p = beg; p < end; p++) {
            int srcn = g_src_sorted[p];
            float4 nb = g_nbg_sorted[p];
            float4 eb = g_ebg_sorted[p];
            float xv = g_h[(size_t)srcn * HD + f];
            if (use_bn) xv = fmaxf(xv * sc + shv, 0.f);
            float m = xv + nb.x * w0 + nb.y * w1 + nb.z * w2 + nb.w * w3
                         + eb.x * e0 + eb.y * e1 + eb.z * e2 + eb.w * e3 + cb;
            m = fmaxf(m, 0.f) + 1e-7f;
            float nM = fmaxf(M, m);
            float corr = __expf(M - nM);
            float ev = __expf(m - nM);
            s = s * corr + ev;
            w = w * corr + ev * m;
            M = nM;
        }
        float aggr = (end > beg) ? w / (s + 1e-16f) : 0.f;
        float val = xc + aggr;
        size_t idx = (size_t)d * HD + f;
        __half h, l;
        split16(val, h, l);
        g_hmh[idx] = h;
        g_hml[idx] = l;
    }
}

// ---------------- BatchNorm statistics (double accumulation) ----------------
__global__ void __launch_bounds__(256) k_bnstats() {
    int f = threadIdx.x;
    int r0 = blockIdx.x * 100;
    double s = 0.0, q = 0.0;
    for (int rr = 0; rr < 100; rr++) {
        float v = g_h[(size_t)(r0 + rr) * HD + f];
        s += (double)v;
        q += (double)v * (double)v;
    }
    atomicAdd(&g_bnsum[f], s);
    atomicAdd(&g_bnsq[f], q);
}

__global__ void k_bncoef(const float* __restrict__ gamma, const float* __restrict__ beta) {
    int f = threadIdx.x;
    double mean = g_bnsum[f] / (double)EG;
    double var = g_bnsq[f] / (double)EG - mean * mean;
    double r = 1.0 / sqrt(var + 1e-5);
    float scl = (float)((double)gamma[f] * r);
    g_bnscale[f] = scl;
    g_bnshift[f] = (float)((double)beta[f] - mean * (double)scl);
}

// ---------------- final: scatter to nodes (with final BN) + graph pooling ----------------
__global__ void __launch_bounds__(256) k_pool(const int* __restrict__ bv) {
    int f = threadIdx.x;
    float sc = g_bnscale[f], sh = g_bnshift[f];
    int n0 = blockIdx.x * 8;
    #pragma unroll 1
    for (int nn = 0; nn < 8; nn++) {
        int n = n0 + nn;
        int beg = g_rowptr_g[n], end = g_rowptr_g[n + 1];
        if (end > beg) {
            float acc = 0.f;
            for (int p = beg; p < end; p++) {
                int e = g_eid_sorted[p];
                acc += g_h[(size_t)e * HD + f] * sc + sh;
            }
            atomicAdd(&g_gsum[(size_t)bv[n] * HD + f], acc);
        }
    }
}

__global__ void k_pred(const float* __restrict__ Wpred, const float* __restrict__ bpred,
                       float* __restrict__ out) {
    __shared__ float red[256];
    int g = blockIdx.x;
    int f = threadIdx.x;
    float c = fmaxf((float)g_cnt[g], 1.0f);
    float v = (g_gsum[(size_t)g * HD + f] / c) * Wpred[f];
    red[f] = v;
    __syncthreads();
    for (int stw = 128; stw > 0; stw >>= 1) {
        if (f < stw) red[f] += red[f + stw];
        __syncthreads();
    }
    if (f == 0) out[g] = red[0] + bpred[0];
}

// ---------------- host ----------------
extern "C" void kernel_launch(void* const* d_in, const int* in_sizes, int n_in,
                              void* d_out, int out_size) {
    const float* xg    = (const float*)d_in[0];
    const float* ea    = (const float*)d_in[1];
    const float* xlg   = (const float*)d_in[2];
    const float* edb   = (const float*)d_in[3];
    const float* ealg  = (const float*)d_in[4];
    const float* Wenc  = (const float*)d_in[5];
    const float* benc  = (const float*)d_in[6];
    const float* Wmsg  = (const float*)d_in[7];
    const float* bmsg  = (const float*)d_in[8];
    const float* Wgnb  = (const float*)d_in[9];
    const float* bgnb  = (const float*)d_in[10];
    const float* Wgeb  = (const float*)d_in[11];
    const float* bgeb  = (const float*)d_in[12];
    const float* Wlnb  = (const float*)d_in[13];
    const float* blnb  = (const float*)d_in[14];
    const float* Wleb  = (const float*)d_in[15];
    const float* bleb  = (const float*)d_in[16];
    const float* W1    = (const float*)d_in[17];
    const float* b1    = (const float*)d_in[18];
    const float* W2    = (const float*)d_in[19];
    const float* b2    = (const float*)d_in[20];
    const float* gamma = (const float*)d_in[21];
    const float* beta  = (const float*)d_in[22];
    const float* Wpred = (const float*)d_in[23];
    const float* bpred = (const float*)d_in[24];
    const int*   eig   = (const int*)d_in[25];
    const int*   eilg  = (const int*)d_in[26];
    const int*   bv    = (const int*)d_in[27];
    float* out = (float*)d_out;

    cudaFuncSetAttribute(k_mgemm, cudaFuncAttributeMaxDynamicSharedMemorySize, MG_SMEM);

    // ---- weight conversion: [K,N] fp32 -> [N,K] fp16 ----
    k_wconv<<<HD / 8, 256>>>(Wmsg,           HD,  HD,  WOFF_P);
    k_wconv<<<HD / 8, 256>>>(Wmsg + HD * HD, HD,  HD,  WOFF_Q);
    for (int l = 0; l < NL; l++) {
        k_wconv<<<HD2 / 8, 256>>>(W1 + (size_t)l * HD * HD2, HD,  HD2,
                                  WOFF_W1 + (size_t)l * 131072);
        k_wconv<<<HD / 8, 256>>>(W2 + (size_t)l * HD2 * HD, HD2, HD,
                                 WOFF_W2 + (size_t)l * 131072);
    }

    // ---- setup: CSRs, basis projections, encoder ----
    int nb_lg = (EG + 1023) / 1024;   // 196
    int nb_g  = (NN + 1023) / 1024;   // 20
    k_zero_setup<<<(EG + 255) / 256, 256>>>();
    k_hist_lg<<<(ELG + 255) / 256, 256>>>(eilg);
    k_hist_g<<<(EG + 255) / 256, 256>>>(eig);
    k_hist_batch<<<(NN + 255) / 256, 256>>>(bv);
    k_scan1<<<nb_lg, 1024>>>(0);
    k_scan2<<<1, 256>>>(nb_lg);
    k_scan3<<<nb_lg, 1024>>>(0);
    k_scan1<<<nb_g, 1024>>>(1);
    k_scan2<<<1, 256>>>(nb_g);
    k_scan3<<<nb_g, 1024>>>(1);
    k_prepcur<<<(EG + 255) / 256, 256>>>();
    k_basis<<<(EG + 255) / 256, 256>>>(edb, Wgnb, bgnb, 0);
    k_basis<<<(ELG + 255) / 256, 256>>>(ealg, Wgeb, bgeb, 1);
    k_scatter_lg<<<(ELG + 255) / 256, 256>>>(eilg);
    k_scatter_g<<<(EG + 255) / 256, 256>>>(eig);
    k_enc<<<NN / 8, 256>>>(xg, Wenc, benc);

    // ---- P/Q node GEMMs + first message embedding ----
    int gpq = (NN + 127) / 128;
    k_mgemm<<<dim3(2, gpq), 256, MG_SMEM>>>(nullptr, NN, HD, HD, 0, /*A=hn*/0, /*C=P*/0, 0, WOFF_P);
    k_mgemm<<<dim3(2, gpq), 256, MG_SMEM>>>(nullptr, NN, HD, HD, 0, 0, /*C=Q*/1, 0, WOFF_Q);
    k_h0<<<EG / 16, 256>>>(ea, xlg, Wmsg, bmsg, eig);

    // ---- layers ----
    int gE = (EG + 127) / 128;
    for (int l = 0; l < NL; l++) {
        if (l > 0) {
            k_zero_bn<<<1, 256>>>();
            k_bnstats<<<EG / 100, 256>>>();
            k_bncoef<<<1, 256>>>(gamma + (l - 1) * HD, beta + (l - 1) * HD);
        }
        k_agg<<<EG / AGG_NPB, 256>>>(Wlnb + l * 4 * HD, blnb + l * HD,
                                     Wleb + l * 4 * HD, bleb + l * HD, l > 0);
        k_mgemm<<<dim3(4, gE), 256, MG_SMEM>>>(b1 + l * HD2, EG, HD2, HD, /*relu*/1,
                                               /*A=hm*/1, /*C=m2 split*/2, 0,
                                               WOFF_W1 + (size_t)l * 131072);
        k_mgemm<<<dim3(2, gE), 256, MG_SMEM>>>(b2 + l * HD, EG, HD, HD2, /*relu*/0,
                                               /*A=m2*/2, /*C=h*/3, /*res*/(l > 0) ? 1 : 0,
                                               WOFF_W2 + (size_t)l * 131072);
    }

    // ---- final BN + scatter-to-nodes + pooling + prediction ----
    k_zero_bn<<<1, 256>>>();
    k_bnstats<<<EG / 100, 256>>>();
    k_bncoef<<<1, 256>>>(gamma + 3 * HD, beta + 3 * HD);
    k_pool<<<NN / 8, 256>>>(bv);
    k_pred<<<NG, 256>>>(Wpred, bpred, out);
}

// round 11
// speedup vs baseline: 1.2691x; 1.2691x over previous
#include <cuda_runtime.h>
#include <cuda_fp16.h>
#include <cstdint>

#define NN   20000
#define EG   200000
#define ELG  400000
#define HD   256
#define HD2  512
#define NL   4
#define NG   128
#define KSB  80   // padded smem row stride in BYTES (64B payload + 16 pad), ldmatrix conflict-free

// ---------------- scratch (device globals; no allocations allowed) ----------------
__device__ float  g_P[NN * HD];
__device__ float  g_Q[NN * HD];
__device__ float  g_h[EG * HD];        // current layer state (pre-BN)
__device__ float4 g_nbg[EG];
__device__ float4 g_ebg[ELG];
__device__ int    g_counts_lg[EG];
__device__ int    g_counts_g[NN];
__device__ int    g_rowptr_lg[EG + 1];
__device__ int    g_rowptr_g[NN + 1];
__device__ int    g_cursor_lg[EG];
__device__ int    g_cursor_g[NN];
__device__ int    g_src_sorted[ELG];
__device__ float4 g_nbg_sorted[ELG];
__device__ float4 g_ebg_sorted[ELG];
__device__ int    g_eid_sorted[EG];
__device__ double g_bnsum[HD];
__device__ double g_bnsq[HD];
__device__ float  g_bnscale[HD];
__device__ float  g_bnshift[HD];
__device__ float  g_gsum[NG * HD];
__device__ int    g_cnt[NG];
__device__ int    g_blksum[256];

// fp16 hi/lo A operands (padded +128 rows; device globals are zero-initialized)
__device__ __half g_hnh[(NN + 128) * HD];
__device__ __half g_hnl[(NN + 128) * HD];
__device__ __half g_hmh[(EG + 128) * HD];
__device__ __half g_hml[(EG + 128) * HD];
__device__ __half g_m2h[(EG + 128) * HD2];
__device__ __half g_m2l[(EG + 128) * HD2];

// weights single fp16, [N,K] K-contiguous
#define WOFF_P  0
#define WOFF_Q  65536
#define WOFF_W1 131072              // + l*131072
#define WOFF_W2 655360              // + l*131072
#define WTOT    1179648
__device__ __half g_Wv[WTOT];

// ---------------- mma / cp.async helpers (sm_80+ PTX, valid on sm_100 base) ----------------
__device__ __forceinline__ void ldsm4(uint32_t addr, uint32_t* r) {
    asm volatile("ldmatrix.sync.aligned.m8n8.x4.shared.b16 {%0,%1,%2,%3}, [%4];"
                 : "=r"(r[0]), "=r"(r[1]), "=r"(r[2]), "=r"(r[3]) : "r"(addr));
}
__device__ __forceinline__ void mma_f16(float* c, const uint32_t* a, uint32_t b0, uint32_t b1) {
    asm volatile("mma.sync.aligned.m16n8k16.row.col.f32.f16.f16.f32 "
                 "{%0,%1,%2,%3}, {%4,%5,%6,%7}, {%8,%9}, {%0,%1,%2,%3};"
                 : "+f"(c[0]), "+f"(c[1]), "+f"(c[2]), "+f"(c[3])
                 : "r"(a[0]), "r"(a[1]), "r"(a[2]), "r"(a[3]), "r"(b0), "r"(b1));
}
__device__ __forceinline__ uint32_t smem_u32(const void* p) {
    uint32_t a;
    asm("{ .reg .u64 t; cvta.to.shared.u64 t, %1; cvt.u32.u64 %0, t; }" : "=r"(a) : "l"(p));
    return a;
}
__device__ __forceinline__ void cpa16(uint32_t s, const void* g) {
    asm volatile("cp.async.cg.shared.global [%0], [%1], 16;" :: "r"(s), "l"(g));
}
#define CP_COMMIT() asm volatile("cp.async.commit_group;" ::: "memory")
#define CP_WAIT1()  asm volatile("cp.async.wait_group 1;" ::: "memory")

// fp16 hi/lo split
__device__ __forceinline__ void split16(float x, __half& h, __half& l) {
    h = __float2half(x);
    l = __float2half(x - __half2float(h));
}

// smem stage layout (bytes): A_hi | A_lo | B, each 128*KSB = 10240
#define SA_HI 0
#define SA_LO 10240
#define SB_V  20480
#define STG   30720
#define NSTG  3
#define MG_SMEM (NSTG * STG)

// ---------------- fp16 2-pass mma GEMM: C[M,N] = A[M,K] @ B[K,N] (+bias, relu, res) ----------
// grid: x = M-tile, y = N-tile (R7/6213 configuration). 2 CTAs/SM for overhead hiding.
__global__ void __launch_bounds__(256, 2) k_mgemm(
    const float* __restrict__ bias,
    int M, int N, int K, int relu, int abuf, int cbuf, int addres, size_t woff)
{
    extern __shared__ char dsm[];
    const __half* Ah_ = (abuf == 0) ? g_hnh : (abuf == 1) ? g_hmh : g_m2h;
    const __half* Al_ = (abuf == 0) ? g_hnl : (abuf == 1) ? g_hml : g_m2l;
    const __half* Bv_ = g_Wv + woff;

    int tid = threadIdx.x, wid = tid >> 5, lid = tid & 31;
    int bm = blockIdx.x * 128;
    int bn = blockIdx.y * 128;
    int wm = (wid >> 2) * 64;
    int wn = (wid & 3) * 32;

    // cp.async: 4 threads/row cover 64 bytes (32 fp16); rows r0 and r0+64
    int r0 = tid >> 2, e0 = (tid & 3) * 8;       // element offset within chunk
    int r1 = r0 + 64;
    const __half* Ah0 = Ah_ + (size_t)(bm + r0) * K + e0;
    const __half* Ah1 = Ah_ + (size_t)(bm + r1) * K + e0;
    const __half* Al0 = Al_ + (size_t)(bm + r0) * K + e0;
    const __half* Al1 = Al_ + (size_t)(bm + r1) * K + e0;
    const __half* Bv0 = Bv_ + (size_t)(bn + r0) * K + e0;
    const __half* Bv1 = Bv_ + (size_t)(bn + r1) * K + e0;
    uint32_t d0 = (uint32_t)(r0 * KSB + e0 * 2);
    uint32_t d1 = (uint32_t)(r1 * KSB + e0 * 2);

    uint32_t sbase = smem_u32(dsm);

    // ldmatrix per-lane offsets (bytes)
    int a_ml = (lid & 7) + ((lid >> 3) & 1) * 8;
    int a_kb = (lid >> 4) * 16;
    int b_nl = (lid & 7) + (lid >> 4) * 8;
    int b_kb = ((lid >> 3) & 1) * 16;
    uint32_t aoff[4], boffm[2];
    #pragma unroll
    for (int mt = 0; mt < 4; mt++)
        aoff[mt] = (uint32_t)((wm + mt * 16 + a_ml) * KSB + a_kb);
    #pragma unroll
    for (int p = 0; p < 2; p++)
        boffm[p] = (uint32_t)((wn + p * 16 + b_nl) * KSB + b_kb);

    float acc[4][4][4];
    #pragma unroll
    for (int i = 0; i < 4; i++)
        #pragma unroll
        for (int j = 0; j < 4; j++)
            #pragma unroll
            for (int q = 0; q < 4; q++) acc[i][j][q] = 0.f;

    int nck = K >> 5;   // chunks of 32 fp16 (64 bytes/row)

    auto load_stage = [&](int s, int c) {
        uint32_t sb = sbase + s * STG;
        int co = c * 32;
        cpa16(sb + SA_HI + d0, Ah0 + co); cpa16(sb + SA_HI + d1, Ah1 + co);
        cpa16(sb + SA_LO + d0, Al0 + co); cpa16(sb + SA_LO + d1, Al1 + co);
        cpa16(sb + SB_V  + d0, Bv0 + co); cpa16(sb + SB_V  + d1, Bv1 + co);
    };

    load_stage(0, 0); CP_COMMIT();
    load_stage(1, 1); CP_COMMIT();

    for (int c = 0; c < nck; c++) {
        CP_WAIT1();
        __syncthreads();
        if (c + 2 < nck) load_stage((c + 2) % NSTG, c + 2);
        CP_COMMIT();
        uint32_t stb = sbase + (c % NSTG) * STG;
        #pragma unroll
        for (int kk = 0; kk < 2; kk++) {
            uint32_t ko = kk * 32;   // 32 bytes = k16 fp16 per mma
            uint32_t ah[4][4], al[4][4], bv[2][4];
            #pragma unroll
            for (int mt = 0; mt < 4; mt++) {
                ldsm4(stb + SA_HI + aoff[mt] + ko, ah[mt]);
                ldsm4(stb + SA_LO + aoff[mt] + ko, al[mt]);
            }
            #pragma unroll
            for (int p = 0; p < 2; p++)
                ldsm4(stb + SB_V + boffm[p] + ko, bv[p]);
            #pragma unroll
            for (int mt = 0; mt < 4; mt++) {
                #pragma unroll
                for (int nt = 0; nt < 4; nt++) {
                    int p = nt >> 1, o = (nt & 1) * 2;
                    mma_f16(acc[mt][nt], ah[mt], bv[p][o], bv[p][o + 1]);   // Ah*B
                    mma_f16(acc[mt][nt], al[mt], bv[p][o], bv[p][o + 1]);   // Al*B
                }
            }
        }
        __syncthreads();
    }

    // ---- epilogue ----
    int l4 = lid >> 2, lc = (lid & 3) * 2;
    #pragma unroll
    for (int mt = 0; mt < 4; mt++) {
        #pragma unroll
        for (int nt = 0; nt < 4; nt++) {
            int m = bm + wm + mt * 16 + l4;
            int n = bn + wn + nt * 8 + lc;
            float2 bia = make_float2(0.f, 0.f);
            if (bias) bia = *(const float2*)&bias[n];
            #pragma unroll
            for (int half_ = 0; half_ < 2; half_++) {
                int mm = m + half_ * 8;
                if (mm < M) {
                    float v0 = acc[mt][nt][half_ * 2 + 0] + bia.x;
                    float v1 = acc[mt][nt][half_ * 2 + 1] + bia.y;
                    if (relu) { v0 = fmaxf(v0, 0.f); v1 = fmaxf(v1, 0.f); }
                    if (cbuf == 2) {
                        // fp16 hi/lo split store to mid2
                        __half h0, l0, h1, l1;
                        split16(v0, h0, l0);
                        split16(v1, h1, l1);
                        __half2 ph; ph.x = h0; ph.y = h1;
                        __half2 pl; pl.x = l0; pl.y = l1;
                        *(__half2*)&g_m2h[(size_t)mm * N + n] = ph;
                        *(__half2*)&g_m2l[(size_t)mm * N + n] = pl;
                    } else {
                        float* C = (cbuf == 0) ? g_P : (cbuf == 1) ? g_Q : g_h;
                        if (addres) {
                            float2 rr = *(const float2*)&g_h[(size_t)mm * N + n];
                            v0 += rr.x; v1 += rr.y;
                        }
                        float2 ov; ov.x = v0; ov.y = v1;
                        *(float2*)&C[(size_t)mm * N + n] = ov;
                    }
                }
            }
        }
    }
}

// ---------------- weight convert: in[K,N] fp32 -> [N,K] fp16 ----------------
__global__ void k_wconv(const float* __restrict__ in, int K, int N, size_t woff) {
    int wid = threadIdx.x >> 5, lane = threadIdx.x & 31;
    int n = blockIdx.x * 8 + wid;
    if (n >= N) return;
    for (int k = lane; k < K; k += 32)
        g_Wv[woff + (size_t)n * K + k] = __float2half(in[(size_t)k * N + n]);
}

// ---------------- setup / zero ----------------
__global__ void k_zero_setup() {
    int i = blockIdx.x * 256 + threadIdx.x;
    if (i < EG)       g_counts_lg[i] = 0;
    if (i < NN)       g_counts_g[i] = 0;
    if (i < NG * HD)  g_gsum[i] = 0.f;
    if (i < NG)       g_cnt[i] = 0;
}

__global__ void k_zero_bn() {
    int f = threadIdx.x;
    g_bnsum[f] = 0.0;
    g_bnsq[f] = 0.0;
}

// ---------------- histograms ----------------
__global__ void k_hist_lg(const int* __restrict__ eilg) {
    int e = blockIdx.x * 256 + threadIdx.x;
    if (e < ELG) atomicAdd(&g_counts_lg[eilg[ELG + e]], 1);
}
__global__ void k_hist_g(const int* __restrict__ eig) {
    int e = blockIdx.x * 256 + threadIdx.x;
    if (e < EG) atomicAdd(&g_counts_g[eig[EG + e]], 1);
}
__global__ void k_hist_batch(const int* __restrict__ bv) {
    int n = blockIdx.x * 256 + threadIdx.x;
    if (n < NN) atomicAdd(&g_cnt[bv[n]], 1);
}

// ---------------- parallel 3-phase exclusive scan ----------------
__global__ void k_scan1(int which) {
    const int* in = (which == 0) ? g_counts_lg : g_counts_g;
    int n = (which == 0) ? EG : NN;
    int b = blockIdx.x, t = threadIdx.x, lane = t & 31, w = t >> 5;
    __shared__ int ws[32];
    int i = b * 1024 + t;
    int v = (i < n) ? in[i] : 0;
    #pragma unroll
    for (int o = 16; o > 0; o >>= 1) v += __shfl_xor_sync(0xFFFFFFFF, v, o);
    if (lane == 0) ws[w] = v;
    __syncthreads();
    if (t == 0) {
        int s = 0;
        #pragma unroll
        for (int k = 0; k < 32; k++) s += ws[k];
        g_blksum[b] = s;
    }
}
__global__ void k_scan2(int nb) {
    __shared__ int ws[8];
    int t = threadIdx.x, lane = t & 31, w = t >> 5;
    int v = (t < nb) ? g_blksum[t] : 0;
    int x = v;
    #pragma unroll
    for (int o = 1; o < 32; o <<= 1) {
        int y = __shfl_up_sync(0xFFFFFFFF, x, o);
        if (lane >= o) x += y;
    }
    if (lane == 31) ws[w] = x;
    __syncthreads();
    if (w == 0 && lane < 8) {
        int s = ws[lane];
        #pragma unroll
        for (int o = 1; o < 8; o <<= 1) {
            int y = __shfl_up_sync(0xFF, s, o);
            if (lane >= o) s += y;
        }
        ws[lane] = s;
    }
    __syncthreads();
    int woff = (w > 0) ? ws[w - 1] : 0;
    if (t < nb) g_blksum[t] = woff + x - v;   // exclusive
}
__global__ void k_scan3(int which) {
    const int* in;
    int* out;
    int n;
    if (which == 0) { in = g_counts_lg; out = g_rowptr_lg; n = EG; }
    else            { in = g_counts_g;  out = g_rowptr_g;  n = NN; }
    __shared__ int ws[32];
    int b = blockIdx.x, t = threadIdx.x, lane = t & 31, w = t >> 5;
    int i = b * 1024 + t;
    int v = (i < n) ? in[i] : 0;
    int x = v;
    #pragma unroll
    for (int o = 1; o < 32; o <<= 1) {
        int y = __shfl_up_sync(0xFFFFFFFF, x, o);
        if (lane >= o) x += y;
    }
    if (lane == 31) ws[w] = x;
    __syncthreads();
    if (w == 0) {
        int s = ws[lane];
        #pragma unroll
        for (int o = 1; o < 32; o <<= 1) {
            int y = __shfl_up_sync(0xFFFFFFFF, s, o);
            if (lane >= o) s += y;
        }
        ws[lane] = s;
    }
    __syncthreads();
    int woff = (w > 0) ? ws[w - 1] : 0;
    int base = g_blksum[b];
    if (i < n) out[i] = base + woff + x - v;
    if (i == n - 1) out[n] = base + woff + x;   // total
}

__global__ void k_prepcur() {
    int i = blockIdx.x * 256 + threadIdx.x;
    if (i < EG) g_cursor_lg[i] = g_rowptr_lg[i];
    if (i < NN) g_cursor_g[i] = g_rowptr_g[i];
}

// ---------------- tiny 4->4 basis projections ----------------
__global__ void k_basis(const float* __restrict__ in, const float* __restrict__ W,
                        const float* __restrict__ b, int which) {
    int R = (which == 0) ? EG : ELG;
    float4* out = (which == 0) ? g_nbg : g_ebg;
    int r = blockIdx.x * 256 + threadIdx.x;
    if (r >= R) return;
    float4 v = ((const float4*)in)[r];
    float4 o;
    o.x = v.x * W[0] + v.y * W[4] + v.z * W[8]  + v.w * W[12] + b[0];
    o.y = v.x * W[1] + v.y * W[5] + v.z * W[9]  + v.w * W[13] + b[1];
    o.z = v.x * W[2] + v.y * W[6] + v.z * W[10] + v.w * W[14] + b[2];
    o.w = v.x * W[3] + v.y * W[7] + v.z * W[11] + v.w * W[15] + b[3];
    out[r] = o;
}

// ---------------- scatter (counting-sort finish) ----------------
__global__ void k_scatter_lg(const int* __restrict__ eilg) {
    int e = blockIdx.x * 256 + threadIdx.x;
    if (e >= ELG) return;
    int s = eilg[e];
    int d = eilg[ELG + e];
    int pos = atomicAdd(&g_cursor_lg[d], 1);
    g_src_sorted[pos] = s;
    g_nbg_sorted[pos] = g_nbg[s];
    g_ebg_sorted[pos] = g_ebg[e];
}
__global__ void k_scatter_g(const int* __restrict__ eig) {
    int e = blockIdx.x * 256 + threadIdx.x;
    if (e >= EG) return;
    int d = eig[EG + e];
    int pos = atomicAdd(&g_cursor_g[d], 1);
    g_eid_sorted[pos] = e;
}

// ---------------- node encoder: h_node = x_g @ W_enc + b_enc (fp16 hi/lo out) ----------------
__global__ void __launch_bounds__(256) k_enc(const float* __restrict__ xg,
                                             const float* __restrict__ Wenc,
                                             const float* __restrict__ benc) {
    __shared__ float xs[8][16];
    int t = threadIdx.x;
    int r0 = blockIdx.x * 8;
    if (t < 128) xs[t >> 4][t & 15] = xg[(r0 + (t >> 4)) * 16 + (t & 15)];
    __syncthreads();
    int f = t;
    float w[16];
    #pragma unroll
    for (int k = 0; k < 16; k++) w[k] = Wenc[k * HD + f];
    float b = benc[f];
    #pragma unroll
    for (int rr = 0; rr < 8; rr++) {
        float acc = b;
        #pragma unroll
        for (int k = 0; k < 16; k++) acc += xs[rr][k] * w[k];
        size_t idx = (size_t)(r0 + rr) * HD + f;
        __half h, l;
        split16(acc, h, l);
        g_hnh[idx] = h;
        g_hnl[idx] = l;
    }
}

// ---------------- first message embedding ----------------
__global__ void __launch_bounds__(256) k_h0(const float* __restrict__ ea,
                                            const float* __restrict__ xlg,
                                            const float* __restrict__ Wmsg,
                                            const float* __restrict__ bmsg,
                                            const int* __restrict__ eig) {
    __shared__ float sea[16][16];
    __shared__ float sxl[16][4];
    __shared__ int ssrc[16], sdst[16];
    int t = threadIdx.x;
    int e0 = blockIdx.x * 16;
    sea[t >> 4][t & 15] = ea[(size_t)e0 * 16 + t];
    if (t < 64) sxl[t >> 2][t & 3] = xlg[(size_t)e0 * 4 + t];
    if (t < 16) { ssrc[t] = eig[e0 + t]; sdst[t] = eig[EG + e0 + t]; }
    __syncthreads();
    int f = t;
    float wme[16];
    #pragma unroll
    for (int k = 0; k < 16; k++) wme[k] = Wmsg[(size_t)(512 + k) * HD + f];
    float wmx[4];
    #pragma unroll
    for (int k = 0; k < 4; k++) wmx[k] = Wmsg[(size_t)(528 + k) * HD + f];
    float bb = bmsg[f];
    #pragma unroll 1
    for (int ee = 0; ee < 16; ee++) {
        int e = e0 + ee;
        int s = ssrc[ee], d = sdst[ee];
        float acc = g_P[(size_t)s * HD + f] + g_Q[(size_t)d * HD + f] + bb;
        #pragma unroll
        for (int k = 0; k < 16; k++) acc += sea[ee][k] * wme[k];
        #pragma unroll
        for (int k = 0; k < 4; k++) acc += sxl[ee][k] * wmx[k];
        g_h[(size_t)e * HD + f] = acc;
    }
}

// ---------------- GENConv aggregation (online softmax, BN folded, fp16 hi/lo out) -------------
#define AGG_NPB 4
__global__ void __launch_bounds__(256) k_agg(const float* __restrict__ Wnb,
                                             const float* __restrict__ bnb,
                                             const float* __restrict__ Web,
                                             const float* __restrict__ beb,
                                             int use_bn) {
    int f = threadIdx.x;
    float w0 = Wnb[f], w1 = Wnb[HD + f], w2 = Wnb[2 * HD + f], w3 = Wnb[3 * HD + f];
    float e0 = Web[f], e1 = Web[HD + f], e2 = Web[2 * HD + f], e3 = Web[3 * HD + f];
    float cb = bnb[f] + beb[f];
    float sc = use_bn ? g_bnscale[f] : 1.f;
    float shv = use_bn ? g_bnshift[f] : 0.f;
    int d0 = blockIdx.x * AGG_NPB;
    const float NEG_INF = __int_as_float(0xff800000);
    #pragma unroll 1
    for (int dd = 0; dd < AGG_NPB; dd++) {
        int d = d0 + dd;
        int beg = g_rowptr_lg[d], end = g_rowptr_lg[d + 1];
        float xc = g_h[(size_t)d * HD + f];
        if (use_bn) xc = fmaxf(xc * sc + shv, 0.f);
        float M = NEG_INF, s = 0.f, w = 0.f;
        for (int p = beg; p < end; p++) {
            int srcn = g_src_sorted[p];
            float4 nb = g_nbg_sorted[p];
            float4 eb = g_ebg_sorted[p];
            float xv = g_h[(size_t)srcn * HD + f];
            if (use_bn) xv = fmaxf(xv * sc + shv, 0.f);
            float m = xv + nb.x * w0 + nb.y * w1 + nb.z * w2 + nb.w * w3
                         + eb.x * e0 + eb.y * e1 + eb.z * e2 + eb.w * e3 + cb;
            m = fmaxf(m, 0.f) + 1e-7f;
            float nM = fmaxf(M, m);
            float corr = __expf(M - nM);
            float ev = __expf(m - nM);
            s = s * corr + ev;
            w = w * corr + ev * m;
            M = nM;
        }
        float aggr = (end > beg) ? w / (s + 1e-16f) : 0.f;
        float val = xc + aggr;
        size_t idx = (size_t)d * HD + f;
        __half h, l;
        split16(val, h, l);
        g_hmh[idx] = h;
        g_hml[idx] = l;
    }
}

// ---------------- BatchNorm statistics (double accumulation) ----------------
__global__ void __launch_bounds__(256) k_bnstats() {
    int f = threadIdx.x;
    int r0 = blockIdx.x * 100;
    double s = 0.0, q = 0.0;
    for (int rr = 0; rr < 100; rr++) {
        float v = g_h[(size_t)(r0 + rr) * HD + f];
        s += (double)v;
        q += (double)v * (double)v;
    }
    atomicAdd(&g_bnsum[f], s);
    atomicAdd(&g_bnsq[f], q);
}

__global__ void k_bncoef(const float* __restrict__ gamma, const float* __restrict__ beta) {
    int f = threadIdx.x;
    double mean = g_bnsum[f] / (double)EG;
    double var = g_bnsq[f] / (double)EG - mean * mean;
    double r = 1.0 / sqrt(var + 1e-5);
    float scl = (float)((double)gamma[f] * r);
    g_bnscale[f] = scl;
    g_bnshift[f] = (float)((double)beta[f] - mean * (double)scl);
}

// ---------------- final: scatter to nodes (with final BN) + graph pooling ----------------
__global__ void __launch_bounds__(256) k_pool(const int* __restrict__ bv) {
    int f = threadIdx.x;
    float sc = g_bnscale[f], sh = g_bnshift[f];
    int n0 = blockIdx.x * 8;
    #pragma unroll 1
    for (int nn = 0; nn < 8; nn++) {
        int n = n0 + nn;
        int beg = g_rowptr_g[n], end = g_rowptr_g[n + 1];
        if (end > beg) {
            float acc = 0.f;
            for (int p = beg; p < end; p++) {
                int e = g_eid_sorted[p];
                acc += g_h[(size_t)e * HD + f] * sc + sh;
            }
            atomicAdd(&g_gsum[(size_t)bv[n] * HD + f], acc);
        }
    }
}

__global__ void k_pred(const float* __restrict__ Wpred, const float* __restrict__ bpred,
                       float* __restrict__ out) {
    __shared__ float red[256];
    int g = blockIdx.x;
    int f = threadIdx.x;
    float c = fmaxf((float)g_cnt[g], 1.0f);
    float v = (g_gsum[(size_t)g * HD + f] / c) * Wpred[f];
    red[f] = v;
    __syncthreads();
    for (int stw = 128; stw > 0; stw >>= 1) {
        if (f < stw) red[f] += red[f + stw];
        __syncthreads();
    }
    if (f == 0) out[g] = red[0] + bpred[0];
}

// ---------------- host ----------------
extern "C" void kernel_launch(void* const* d_in, const int* in_sizes, int n_in,
                              void* d_out, int out_size) {
    const float* xg    = (const float*)d_in[0];
    const float* ea    = (const float*)d_in[1];
    const float* xlg   = (const float*)d_in[2];
    const float* edb   = (const float*)d_in[3];
    const float* ealg  = (const float*)d_in[4];
    const float* Wenc  = (const float*)d_in[5];
    const float* benc  = (const float*)d_in[6];
    const float* Wmsg  = (const float*)d_in[7];
    const float* bmsg  = (const float*)d_in[8];
    const float* Wgnb  = (const float*)d_in[9];
    const float* bgnb  = (const float*)d_in[10];
    const float* Wgeb  = (const float*)d_in[11];
    const float* bgeb  = (const float*)d_in[12];
    const float* Wlnb  = (const float*)d_in[13];
    const float* blnb  = (const float*)d_in[14];
    const float* Wleb  = (const float*)d_in[15];
    const float* bleb  = (const float*)d_in[16];
    const float* W1    = (const float*)d_in[17];
    const float* b1    = (const float*)d_in[18];
    const float* W2    = (const float*)d_in[19];
    const float* b2    = (const float*)d_in[20];
    const float* gamma = (const float*)d_in[21];
    const float* beta  = (const float*)d_in[22];
    const float* Wpred = (const float*)d_in[23];
    const float* bpred = (const float*)d_in[24];
    const int*   eig   = (const int*)d_in[25];
    const int*   eilg  = (const int*)d_in[26];
    const int*   bv    = (const int*)d_in[27];
    float* out = (float*)d_out;

    cudaFuncSetAttribute(k_mgemm, cudaFuncAttributeMaxDynamicSharedMemorySize, MG_SMEM);

    // ---- weight conversion: [K,N] fp32 -> [N,K] fp16 ----
    k_wconv<<<HD / 8, 256>>>(Wmsg,           HD,  HD,  WOFF_P);
    k_wconv<<<HD / 8, 256>>>(Wmsg + HD * HD, HD,  HD,  WOFF_Q);
    for (int l = 0; l < NL; l++) {
        k_wconv<<<HD2 / 8, 256>>>(W1 + (size_t)l * HD * HD2, HD,  HD2,
                                  WOFF_W1 + (size_t)l * 131072);
        k_wconv<<<HD / 8, 256>>>(W2 + (size_t)l * HD2 * HD, HD2, HD,
                                 WOFF_W2 + (size_t)l * 131072);
    }

    // ---- setup: CSRs, basis projections, encoder ----
    int nb_lg = (EG + 1023) / 1024;   // 196
    int nb_g  = (NN + 1023) / 1024;   // 20
    k_zero_setup<<<(EG + 255) / 256, 256>>>();
    k_hist_lg<<<(ELG + 255) / 256, 256>>>(eilg);
    k_hist_g<<<(EG + 255) / 256, 256>>>(eig);
    k_hist_batch<<<(NN + 255) / 256, 256>>>(bv);
    k_scan1<<<nb_lg, 1024>>>(0);
    k_scan2<<<1, 256>>>(nb_lg);
    k_scan3<<<nb_lg, 1024>>>(0);
    k_scan1<<<nb_g, 1024>>>(1);
    k_scan2<<<1, 256>>>(nb_g);
    k_scan3<<<nb_g, 1024>>>(1);
    k_prepcur<<<(EG + 255) / 256, 256>>>();
    k_basis<<<(EG + 255) / 256, 256>>>(edb, Wgnb, bgnb, 0);
    k_basis<<<(ELG + 255) / 256, 256>>>(ealg, Wgeb, bgeb, 1);
    k_scatter_lg<<<(ELG + 255) / 256, 256>>>(eilg);
    k_scatter_g<<<(EG + 255) / 256, 256>>>(eig);
    k_enc<<<NN / 8, 256>>>(xg, Wenc, benc);

    // ---- P/Q node GEMMs + first message embedding ----
    int gpq = (NN + 127) / 128;
    k_mgemm<<<dim3(gpq, 2), 256, MG_SMEM>>>(nullptr, NN, HD, HD, 0, /*A=hn*/0, /*C=P*/0, 0, WOFF_P);
    k_mgemm<<<dim3(gpq, 2), 256, MG_SMEM>>>(nullptr, NN, HD, HD, 0, 0, /*C=Q*/1, 0, WOFF_Q);
    k_h0<<<EG / 16, 256>>>(ea, xlg, Wmsg, bmsg, eig);

    // ---- layers ----
    int gE = (EG + 127) / 128;
    for (int l = 0; l < NL; l++) {
        if (l > 0) {
            k_zero_bn<<<1, 256>>>();
            k_bnstats<<<EG / 100, 256>>>();
            k_bncoef<<<1, 256>>>(gamma + (l - 1) * HD, beta + (l - 1) * HD);
        }
        k_agg<<<EG / AGG_NPB, 256>>>(Wlnb + l * 4 * HD, blnb + l * HD,
                                     Wleb + l * 4 * HD, bleb + l * HD, l > 0);
        k_mgemm<<<dim3(gE, 4), 256, MG_SMEM>>>(b1 + l * HD2, EG, HD2, HD, /*relu*/1,
                                               /*A=hm*/1, /*C=m2 split*/2, 0,
                                               WOFF_W1 + (size_t)l * 131072);
        k_mgemm<<<dim3(gE, 2), 256, MG_SMEM>>>(b2 + l * HD, EG, HD, HD2, /*relu*/0,
                                               /*A=m2*/2, /*C=h*/3, /*res*/(l > 0) ? 1 : 0,
                                               WOFF_W2 + (size_t)l * 131072);
    }

    // ---- final BN + scatter-to-nodes + pooling + prediction ----
    k_zero_bn<<<1, 256>>>();
    k_bnstats<<<EG / 100, 256>>>();
    k_bncoef<<<1, 256>>>(gamma + 3 * HD, beta + 3 * HD);
    k_pool<<<NN / 8, 256>>>(bv);
    k_pred<<<NG, 256>>>(Wpred, bpred, out);
}

// round 12
// speedup vs baseline: 1.3116x; 1.0335x over previous
#include <cuda_runtime.h>
#include <cuda_fp16.h>
#include <cstdint>

#define NN   20000
#define EG   200000
#define ELG  400000
#define HD   256
#define HD2  512
#define NL   4
#define NG   128
#define KSB  80   // padded smem row stride in BYTES (64B payload + 16 pad), ldmatrix conflict-free

// ---------------- scratch (device globals; no allocations allowed) ----------------
__device__ float  g_P[NN * HD];
__device__ float  g_Q[NN * HD];
__device__ float  g_h[EG * HD];        // current layer state (pre-BN)
__device__ float4 g_nbg[EG];
__device__ float4 g_ebg[ELG];
__device__ int    g_counts_lg[EG];
__device__ int    g_counts_g[NN];
__device__ int    g_rowptr_lg[EG + 1];
__device__ int    g_rowptr_g[NN + 1];
__device__ int    g_cursor_lg[EG];
__device__ int    g_cursor_g[NN];
__device__ int    g_src_sorted[ELG];
__device__ float4 g_nbg_sorted[ELG];
__device__ float4 g_ebg_sorted[ELG];
__device__ int    g_eid_sorted[EG];
__device__ double g_bnsum[HD];
__device__ double g_bnsq[HD];
__device__ float  g_bnscale[HD];
__device__ float  g_bnshift[HD];
__device__ float  g_gsum[NG * HD];
__device__ int    g_cnt[NG];
__device__ int    g_blksum[256];

// fp16 hi/lo A operands (padded +128 rows; device globals are zero-initialized)
__device__ __half g_hnh[(NN + 128) * HD];
__device__ __half g_hnl[(NN + 128) * HD];
__device__ __half g_hmh[(EG + 128) * HD];
__device__ __half g_hml[(EG + 128) * HD];
__device__ __half g_m2h[(EG + 128) * HD2];
__device__ __half g_m2l[(EG + 128) * HD2];

// weights single fp16, [N,K] K-contiguous
#define WOFF_P  0
#define WOFF_Q  65536
#define WOFF_W1 131072              // + l*131072
#define WOFF_W2 655360              // + l*131072
#define WTOT    1179648
__device__ __half g_Wv[WTOT];

// ---------------- mma / cp.async helpers (sm_80+ PTX, valid on sm_100 base) ----------------
__device__ __forceinline__ void ldsm4(uint32_t addr, uint32_t* r) {
    asm volatile("ldmatrix.sync.aligned.m8n8.x4.shared.b16 {%0,%1,%2,%3}, [%4];"
                 : "=r"(r[0]), "=r"(r[1]), "=r"(r[2]), "=r"(r[3]) : "r"(addr));
}
__device__ __forceinline__ void mma_f16(float* c, const uint32_t* a, uint32_t b0, uint32_t b1) {
    asm volatile("mma.sync.aligned.m16n8k16.row.col.f32.f16.f16.f32 "
                 "{%0,%1,%2,%3}, {%4,%5,%6,%7}, {%8,%9}, {%0,%1,%2,%3};"
                 : "+f"(c[0]), "+f"(c[1]), "+f"(c[2]), "+f"(c[3])
                 : "r"(a[0]), "r"(a[1]), "r"(a[2]), "r"(a[3]), "r"(b0), "r"(b1));
}
__device__ __forceinline__ uint32_t smem_u32(const void* p) {
    uint32_t a;
    asm("{ .reg .u64 t; cvta.to.shared.u64 t, %1; cvt.u32.u64 %0, t; }" : "=r"(a) : "l"(p));
    return a;
}
__device__ __forceinline__ void cpa16(uint32_t s, const void* g) {
    asm volatile("cp.async.cg.shared.global [%0], [%1], 16;" :: "r"(s), "l"(g));
}
#define CP_COMMIT() asm volatile("cp.async.commit_group;" ::: "memory")
#define CP_WAIT1()  asm volatile("cp.async.wait_group 1;" ::: "memory")

// fp16 hi/lo split
__device__ __forceinline__ void split16(float x, __half& h, __half& l) {
    h = __float2half(x);
    l = __float2half(x - __half2float(h));
}

// smem stage layout (bytes): A_hi | A_lo | B, each 128*KSB = 10240
#define SA_HI 0
#define SA_LO 10240
#define SB_V  20480
#define STG   30720
#define NSTG  3
#define MG_SMEM (NSTG * STG)

// ---------------- fp16 2-pass mma GEMM: C[M,N] = A[M,K] @ B[K,N] (+bias, relu, res) ----------
// grid: x = M-tile, y = N-tile. 2 CTAs/SM. cbuf==3 additionally accumulates BN stats (fused).
__global__ void __launch_bounds__(256, 2) k_mgemm(
    const float* __restrict__ bias,
    int M, int N, int K, int relu, int abuf, int cbuf, int addres, size_t woff)
{
    extern __shared__ char dsm[];
    const __half* Ah_ = (abuf == 0) ? g_hnh : (abuf == 1) ? g_hmh : g_m2h;
    const __half* Al_ = (abuf == 0) ? g_hnl : (abuf == 1) ? g_hml : g_m2l;
    const __half* Bv_ = g_Wv + woff;

    int tid = threadIdx.x, wid = tid >> 5, lid = tid & 31;
    int bm = blockIdx.x * 128;
    int bn = blockIdx.y * 128;
    int wm = (wid >> 2) * 64;
    int wn = (wid & 3) * 32;

    // cp.async: 4 threads/row cover 64 bytes (32 fp16); rows r0 and r0+64
    int r0 = tid >> 2, e0 = (tid & 3) * 8;       // element offset within chunk
    int r1 = r0 + 64;
    const __half* Ah0 = Ah_ + (size_t)(bm + r0) * K + e0;
    const __half* Ah1 = Ah_ + (size_t)(bm + r1) * K + e0;
    const __half* Al0 = Al_ + (size_t)(bm + r0) * K + e0;
    const __half* Al1 = Al_ + (size_t)(bm + r1) * K + e0;
    const __half* Bv0 = Bv_ + (size_t)(bn + r0) * K + e0;
    const __half* Bv1 = Bv_ + (size_t)(bn + r1) * K + e0;
    uint32_t d0 = (uint32_t)(r0 * KSB + e0 * 2);
    uint32_t d1 = (uint32_t)(r1 * KSB + e0 * 2);

    uint32_t sbase = smem_u32(dsm);

    // ldmatrix per-lane offsets (bytes)
    int a_ml = (lid & 7) + ((lid >> 3) & 1) * 8;
    int a_kb = (lid >> 4) * 16;
    int b_nl = (lid & 7) + (lid >> 4) * 8;
    int b_kb = ((lid >> 3) & 1) * 16;
    uint32_t aoff[4], boffm[2];
    #pragma unroll
    for (int mt = 0; mt < 4; mt++)
        aoff[mt] = (uint32_t)((wm + mt * 16 + a_ml) * KSB + a_kb);
    #pragma unroll
    for (int p = 0; p < 2; p++)
        boffm[p] = (uint32_t)((wn + p * 16 + b_nl) * KSB + b_kb);

    float acc[4][4][4];
    #pragma unroll
    for (int i = 0; i < 4; i++)
        #pragma unroll
        for (int j = 0; j < 4; j++)
            #pragma unroll
            for (int q = 0; q < 4; q++) acc[i][j][q] = 0.f;

    int nck = K >> 5;   // chunks of 32 fp16 (64 bytes/row)

    auto load_stage = [&](int s, int c) {
        uint32_t sb = sbase + s * STG;
        int co = c * 32;
        cpa16(sb + SA_HI + d0, Ah0 + co); cpa16(sb + SA_HI + d1, Ah1 + co);
        cpa16(sb + SA_LO + d0, Al0 + co); cpa16(sb + SA_LO + d1, Al1 + co);
        cpa16(sb + SB_V  + d0, Bv0 + co); cpa16(sb + SB_V  + d1, Bv1 + co);
    };

    load_stage(0, 0); CP_COMMIT();
    load_stage(1, 1); CP_COMMIT();

    for (int c = 0; c < nck; c++) {
        CP_WAIT1();
        __syncthreads();
        if (c + 2 < nck) load_stage((c + 2) % NSTG, c + 2);
        CP_COMMIT();
        uint32_t stb = sbase + (c % NSTG) * STG;
        #pragma unroll
        for (int kk = 0; kk < 2; kk++) {
            uint32_t ko = kk * 32;   // 32 bytes = k16 fp16 per mma
            uint32_t ah[4][4], al[4][4], bv[2][4];
            #pragma unroll
            for (int mt = 0; mt < 4; mt++) {
                ldsm4(stb + SA_HI + aoff[mt] + ko, ah[mt]);
                ldsm4(stb + SA_LO + aoff[mt] + ko, al[mt]);
            }
            #pragma unroll
            for (int p = 0; p < 2; p++)
                ldsm4(stb + SB_V + boffm[p] + ko, bv[p]);
            #pragma unroll
            for (int mt = 0; mt < 4; mt++) {
                #pragma unroll
                for (int nt = 0; nt < 4; nt++) {
                    int p = nt >> 1, o = (nt & 1) * 2;
                    mma_f16(acc[mt][nt], ah[mt], bv[p][o], bv[p][o + 1]);   // Ah*B
                    mma_f16(acc[mt][nt], al[mt], bv[p][o], bv[p][o + 1]);   // Al*B
                }
            }
        }
        __syncthreads();
    }

    // ---- epilogue ----
    int l4 = lid >> 2, lc = (lid & 3) * 2;
    float cs[8], cq[8];
    #pragma unroll
    for (int i = 0; i < 8; i++) { cs[i] = 0.f; cq[i] = 0.f; }

    #pragma unroll
    for (int mt = 0; mt < 4; mt++) {
        #pragma unroll
        for (int nt = 0; nt < 4; nt++) {
            int m = bm + wm + mt * 16 + l4;
            int n = bn + wn + nt * 8 + lc;
            float2 bia = make_float2(0.f, 0.f);
            if (bias) bia = *(const float2*)&bias[n];
            #pragma unroll
            for (int half_ = 0; half_ < 2; half_++) {
                int mm = m + half_ * 8;
                if (mm < M) {
                    float v0 = acc[mt][nt][half_ * 2 + 0] + bia.x;
                    float v1 = acc[mt][nt][half_ * 2 + 1] + bia.y;
                    if (relu) { v0 = fmaxf(v0, 0.f); v1 = fmaxf(v1, 0.f); }
                    if (cbuf == 2) {
                        // fp16 hi/lo split store to mid2
                        __half h0, l0, h1, l1;
                        split16(v0, h0, l0);
                        split16(v1, h1, l1);
                        __half2 ph; ph.x = h0; ph.y = h1;
                        __half2 pl; pl.x = l0; pl.y = l1;
                        *(__half2*)&g_m2h[(size_t)mm * N + n] = ph;
                        *(__half2*)&g_m2l[(size_t)mm * N + n] = pl;
                    } else {
                        float* C = (cbuf == 0) ? g_P : (cbuf == 1) ? g_Q : g_h;
                        if (addres) {
                            float2 rr = *(const float2*)&g_h[(size_t)mm * N + n];
                            v0 += rr.x; v1 += rr.y;
                        }
                        float2 ov; ov.x = v0; ov.y = v1;
                        *(float2*)&C[(size_t)mm * N + n] = ov;
                        if (cbuf == 3) {
                            cs[nt * 2 + 0] += v0; cq[nt * 2 + 0] += v0 * v0;
                            cs[nt * 2 + 1] += v1; cq[nt * 2 + 1] += v1 * v1;
                        }
                    }
                }
            }
        }
    }

    // ---- fused BN stats reduction (cbuf==3 only) ----
    if (cbuf == 3) {
        // reduce over the 8 row-lanes (l4) within the warp: strides 4,8,16
        #pragma unroll
        for (int i = 0; i < 8; i++) {
            #pragma unroll
            for (int o = 4; o < 32; o <<= 1) {
                cs[i] += __shfl_down_sync(0xFFFFFFFF, cs[i], o);
                cq[i] += __shfl_down_sync(0xFFFFFFFF, cq[i], o);
            }
        }
        float* s_sum = (float*)dsm;             // 128 floats
        float* s_sq  = (float*)(dsm + 512);     // 128 floats
        if (tid < 128) { s_sum[tid] = 0.f; s_sq[tid] = 0.f; }
        __syncthreads();
        if (lid < 4) {
            #pragma unroll
            for (int nt = 0; nt < 4; nt++) {
                int col = wn + nt * 8 + lid * 2;   // local 0..127
                atomicAdd(&s_sum[col],     cs[nt * 2 + 0]);
                atomicAdd(&s_sq[col],      cq[nt * 2 + 0]);
                atomicAdd(&s_sum[col + 1], cs[nt * 2 + 1]);
                atomicAdd(&s_sq[col + 1],  cq[nt * 2 + 1]);
            }
        }
        __syncthreads();
        if (tid < 128) {
            atomicAdd(&g_bnsum[bn + tid], (double)s_sum[tid]);
            atomicAdd(&g_bnsq[bn + tid],  (double)s_sq[tid]);
        }
    }
}

// ---------------- weight convert: in[K,N] fp32 -> [N,K] fp16 ----------------
__global__ void k_wconv(const float* __restrict__ in, int K, int N, size_t woff) {
    int wid = threadIdx.x >> 5, lane = threadIdx.x & 31;
    int n = blockIdx.x * 8 + wid;
    if (n >= N) return;
    for (int k = lane; k < K; k += 32)
        g_Wv[woff + (size_t)n * K + k] = __float2half(in[(size_t)k * N + n]);
}

// ---------------- setup / zero ----------------
__global__ void k_zero_setup() {
    int i = blockIdx.x * 256 + threadIdx.x;
    if (i < EG)       g_counts_lg[i] = 0;
    if (i < NN)       g_counts_g[i] = 0;
    if (i < NG * HD)  g_gsum[i] = 0.f;
    if (i < NG)       g_cnt[i] = 0;
}

__global__ void k_zero_bn() {
    int f = threadIdx.x;
    g_bnsum[f] = 0.0;
    g_bnsq[f] = 0.0;
}

// ---------------- histograms ----------------
__global__ void k_hist_lg(const int* __restrict__ eilg) {
    int e = blockIdx.x * 256 + threadIdx.x;
    if (e < ELG) atomicAdd(&g_counts_lg[eilg[ELG + e]], 1);
}
__global__ void k_hist_g(const int* __restrict__ eig) {
    int e = blockIdx.x * 256 + threadIdx.x;
    if (e < EG) atomicAdd(&g_counts_g[eig[EG + e]], 1);
}
__global__ void k_hist_batch(const int* __restrict__ bv) {
    int n = blockIdx.x * 256 + threadIdx.x;
    if (n < NN) atomicAdd(&g_cnt[bv[n]], 1);
}

// ---------------- parallel 3-phase exclusive scan ----------------
__global__ void k_scan1(int which) {
    const int* in = (which == 0) ? g_counts_lg : g_counts_g;
    int n = (which == 0) ? EG : NN;
    int b = blockIdx.x, t = threadIdx.x, lane = t & 31, w = t >> 5;
    __shared__ int ws[32];
    int i = b * 1024 + t;
    int v = (i < n) ? in[i] : 0;
    #pragma unroll
    for (int o = 16; o > 0; o >>= 1) v += __shfl_xor_sync(0xFFFFFFFF, v, o);
    if (lane == 0) ws[w] = v;
    __syncthreads();
    if (t == 0) {
        int s = 0;
        #pragma unroll
        for (int k = 0; k < 32; k++) s += ws[k];
        g_blksum[b] = s;
    }
}
__global__ void k_scan2(int nb) {
    __shared__ int ws[8];
    int t = threadIdx.x, lane = t & 31, w = t >> 5;
    int v = (t < nb) ? g_blksum[t] : 0;
    int x = v;
    #pragma unroll
    for (int o = 1; o < 32; o <<= 1) {
        int y = __shfl_up_sync(0xFFFFFFFF, x, o);
        if (lane >= o) x += y;
    }
    if (lane == 31) ws[w] = x;
    __syncthreads();
    if (w == 0 && lane < 8) {
        int s = ws[lane];
        #pragma unroll
        for (int o = 1; o < 8; o <<= 1) {
            int y = __shfl_up_sync(0xFF, s, o);
            if (lane >= o) s += y;
        }
        ws[lane] = s;
    }
    __syncthreads();
    int woff = (w > 0) ? ws[w - 1] : 0;
    if (t < nb) g_blksum[t] = woff + x - v;   // exclusive
}
__global__ void k_scan3(int which) {
    const int* in;
    int* out;
    int n;
    if (which == 0) { in = g_counts_lg; out = g_rowptr_lg; n = EG; }
    else            { in = g_counts_g;  out = g_rowptr_g;  n = NN; }
    __shared__ int ws[32];
    int b = blockIdx.x, t = threadIdx.x, lane = t & 31, w = t >> 5;
    int i = b * 1024 + t;
    int v = (i < n) ? in[i] : 0;
    int x = v;
    #pragma unroll
    for (int o = 1; o < 32; o <<= 1) {
        int y = __shfl_up_sync(0xFFFFFFFF, x, o);
        if (lane >= o) x += y;
    }
    if (lane == 31) ws[w] = x;
    __syncthreads();
    if (w == 0) {
        int s = ws[lane];
        #pragma unroll
        for (int o = 1; o < 32; o <<= 1) {
            int y = __shfl_up_sync(0xFFFFFFFF, s, o);
            if (lane >= o) s += y;
        }
        ws[lane] = s;
    }
    __syncthreads();
    int woff = (w > 0) ? ws[w - 1] : 0;
    int base = g_blksum[b];
    if (i < n) out[i] = base + woff + x - v;
    if (i == n - 1) out[n] = base + woff + x;   // total
}

__global__ void k_prepcur() {
    int i = blockIdx.x * 256 + threadIdx.x;
    if (i < EG) g_cursor_lg[i] = g_rowptr_lg[i];
    if (i < NN) g_cursor_g[i] = g_rowptr_g[i];
}

// ---------------- tiny 4->4 basis projections ----------------
__global__ void k_basis(const float* __restrict__ in, const float* __restrict__ W,
                        const float* __restrict__ b, int which) {
    int R = (which == 0) ? EG : ELG;
    float4* out = (which == 0) ? g_nbg : g_ebg;
    int r = blockIdx.x * 256 + threadIdx.x;
    if (r >= R) return;
    float4 v = ((const float4*)in)[r];
    float4 o;
    o.x = v.x * W[0] + v.y * W[4] + v.z * W[8]  + v.w * W[12] + b[0];
    o.y = v.x * W[1] + v.y * W[5] + v.z * W[9]  + v.w * W[13] + b[1];
    o.z = v.x * W[2] + v.y * W[6] + v.z * W[10] + v.w * W[14] + b[2];
    o.w = v.x * W[3] + v.y * W[7] + v.z * W[11] + v.w * W[15] + b[3];
    out[r] = o;
}

// ---------------- scatter (counting-sort finish) ----------------
__global__ void k_scatter_lg(const int* __restrict__ eilg) {
    int e = blockIdx.x * 256 + threadIdx.x;
    if (e >= ELG) return;
    int s = eilg[e];
    int d = eilg[ELG + e];
    int pos = atomicAdd(&g_cursor_lg[d], 1);
    g_src_sorted[pos] = s;
    g_nbg_sorted[pos] = g_nbg[s];
    g_ebg_sorted[pos] = g_ebg[e];
}
__global__ void k_scatter_g(const int* __restrict__ eig) {
    int e = blockIdx.x * 256 + threadIdx.x;
    if (e >= EG) return;
    int d = eig[EG + e];
    int pos = atomicAdd(&g_cursor_g[d], 1);
    g_eid_sorted[pos] = e;
}

// ---------------- node encoder: h_node = x_g @ W_enc + b_enc (fp16 hi/lo out) ----------------
__global__ void __launch_bounds__(256) k_enc(const float* __restrict__ xg,
                                             const float* __restrict__ Wenc,
                                             const float* __restrict__ benc) {
    __shared__ float xs[8][16];
    int t = threadIdx.x;
    int r0 = blockIdx.x * 8;
    if (t < 128) xs[t >> 4][t & 15] = xg[(r0 + (t >> 4)) * 16 + (t & 15)];
    __syncthreads();
    int f = t;
    float w[16];
    #pragma unroll
    for (int k = 0; k < 16; k++) w[k] = Wenc[k * HD + f];
    float b = benc[f];
    #pragma unroll
    for (int rr = 0; rr < 8; rr++) {
        float acc = b;
        #pragma unroll
        for (int k = 0; k < 16; k++) acc += xs[rr][k] * w[k];
        size_t idx = (size_t)(r0 + rr) * HD + f;
        __half h, l;
        split16(acc, h, l);
        g_hnh[idx] = h;
        g_hnl[idx] = l;
    }
}

// ---------------- first message embedding ----------------
__global__ void __launch_bounds__(256) k_h0(const float* __restrict__ ea,
                                            const float* __restrict__ xlg,
                                            const float* __restrict__ Wmsg,
                                            const float* __restrict__ bmsg,
                                            const int* __restrict__ eig) {
    __shared__ float sea[16][16];
    __shared__ float sxl[16][4];
    __shared__ int ssrc[16], sdst[16];
    int t = threadIdx.x;
    int e0 = blockIdx.x * 16;
    sea[t >> 4][t & 15] = ea[(size_t)e0 * 16 + t];
    if (t < 64) sxl[t >> 2][t & 3] = xlg[(size_t)e0 * 4 + t];
    if (t < 16) { ssrc[t] = eig[e0 + t]; sdst[t] = eig[EG + e0 + t]; }
    __syncthreads();
    int f = t;
    float wme[16];
    #pragma unroll
    for (int k = 0; k < 16; k++) wme[k] = Wmsg[(size_t)(512 + k) * HD + f];
    float wmx[4];
    #pragma unroll
    for (int k = 0; k < 4; k++) wmx[k] = Wmsg[(size_t)(528 + k) * HD + f];
    float bb = bmsg[f];
    #pragma unroll 1
    for (int ee = 0; ee < 16; ee++) {
        int e = e0 + ee;
        int s = ssrc[ee], d = sdst[ee];
        float acc = g_P[(size_t)s * HD + f] + g_Q[(size_t)d * HD + f] + bb;
        #pragma unroll
        for (int k = 0; k < 16; k++) acc += sea[ee][k] * wme[k];
        #pragma unroll
        for (int k = 0; k < 4; k++) acc += sxl[ee][k] * wmx[k];
        g_h[(size_t)e * HD + f] = acc;
    }
}

// ---------------- GENConv aggregation (online softmax, BN folded, fp16 hi/lo out) -------------
#define AGG_NPB 4
__global__ void __launch_bounds__(256) k_agg(const float* __restrict__ Wnb,
                                             const float* __restrict__ bnb,
                                             const float* __restrict__ Web,
                                             const float* __restrict__ beb,
                                             int use_bn) {
    int f = threadIdx.x;
    float w0 = Wnb[f], w1 = Wnb[HD + f], w2 = Wnb[2 * HD + f], w3 = Wnb[3 * HD + f];
    float e0 = Web[f], e1 = Web[HD + f], e2 = Web[2 * HD + f], e3 = Web[3 * HD + f];
    float cb = bnb[f] + beb[f];
    float sc = use_bn ? g_bnscale[f] : 1.f;
    float shv = use_bn ? g_bnshift[f] : 0.f;
    int d0 = blockIdx.x * AGG_NPB;
    const float NEG_INF = __int_as_float(0xff800000);
    #pragma unroll 1
    for (int dd = 0; dd < AGG_NPB; dd++) {
        int d = d0 + dd;
        int beg = g_rowptr_lg[d], end = g_rowptr_lg[d + 1];
        float xc = g_h[(size_t)d * HD + f];
        if (use_bn) xc = fmaxf(xc * sc + shv, 0.f);
        float M = NEG_INF, s = 0.f, w = 0.f;
        for (int p = beg; p < end; p++) {
            int srcn = g_src_sorted[p];
            float4 nb = g_nbg_sorted[p];
            float4 eb = g_ebg_sorted[p];
            float xv = g_h[(size_t)srcn * HD + f];
            if (use_bn) xv = fmaxf(xv * sc + shv, 0.f);
            float m = xv + nb.x * w0 + nb.y * w1 + nb.z * w2 + nb.w * w3
                         + eb.x * e0 + eb.y * e1 + eb.z * e2 + eb.w * e3 + cb;
            m = fmaxf(m, 0.f) + 1e-7f;
            float nM = fmaxf(M, m);
            float corr = __expf(M - nM);
            float ev = __expf(m - nM);
            s = s * corr + ev;
            w = w * corr + ev * m;
            M = nM;
        }
        float aggr = (end > beg) ? w / (s + 1e-16f) : 0.f;
        float val = xc + aggr;
        size_t idx = (size_t)d * HD + f;
        __half h, l;
        split16(val, h, l);
        g_hmh[idx] = h;
        g_hml[idx] = l;
    }
}

__global__ void k_bncoef(const float* __restrict__ gamma, const float* __restrict__ beta) {
    int f = threadIdx.x;
    double mean = g_bnsum[f] / (double)EG;
    double var = g_bnsq[f] / (double)EG - mean * mean;
    double r = 1.0 / sqrt(var + 1e-5);
    float scl = (float)((double)gamma[f] * r);
    g_bnscale[f] = scl;
    g_bnshift[f] = (float)((double)beta[f] - mean * (double)scl);
}

// ---------------- final: scatter to nodes (with final BN) + graph pooling ----------------
__global__ void __launch_bounds__(256) k_pool(const int* __restrict__ bv) {
    int f = threadIdx.x;
    float sc = g_bnscale[f], sh = g_bnshift[f];
    int n0 = blockIdx.x * 8;
    #pragma unroll 1
    for (int nn = 0; nn < 8; nn++) {
        int n = n0 + nn;
        int beg = g_rowptr_g[n], end = g_rowptr_g[n + 1];
        if (end > beg) {
            float acc = 0.f;
            for (int p = beg; p < end; p++) {
                int e = g_eid_sorted[p];
                acc += g_h[(size_t)e * HD + f] * sc + sh;
            }
            atomicAdd(&g_gsum[(size_t)bv[n] * HD + f], acc);
        }
    }
}

__global__ void k_pred(const float* __restrict__ Wpred, const float* __restrict__ bpred,
                       float* __restrict__ out) {
    __shared__ float red[256];
    int g = blockIdx.x;
    int f = threadIdx.x;
    float c = fmaxf((float)g_cnt[g], 1.0f);
    float v = (g_gsum[(size_t)g * HD + f] / c) * Wpred[f];
    red[f] = v;
    __syncthreads();
    for (int stw = 128; stw > 0; stw >>= 1) {
        if (f < stw) red[f] += red[f + stw];
        __syncthreads();
    }
    if (f == 0) out[g] = red[0] + bpred[0];
}

// ---------------- host ----------------
extern "C" void kernel_launch(void* const* d_in, const int* in_sizes, int n_in,
                              void* d_out, int out_size) {
    const float* xg    = (const float*)d_in[0];
    const float* ea    = (const float*)d_in[1];
    const float* xlg   = (const float*)d_in[2];
    const float* edb   = (const float*)d_in[3];
    const float* ealg  = (const float*)d_in[4];
    const float* Wenc  = (const float*)d_in[5];
    const float* benc  = (const float*)d_in[6];
    const float* Wmsg  = (const float*)d_in[7];
    const float* bmsg  = (const float*)d_in[8];
    const float* Wgnb  = (const float*)d_in[9];
    const float* bgnb  = (const float*)d_in[10];
    const float* Wgeb  = (const float*)d_in[11];
    const float* bgeb  = (const float*)d_in[12];
    const float* Wlnb  = (const float*)d_in[13];
    const float* blnb  = (const float*)d_in[14];
    const float* Wleb  = (const float*)d_in[15];
    const float* bleb  = (const float*)d_in[16];
    const float* W1    = (const float*)d_in[17];
    const float* b1    = (const float*)d_in[18];
    const float* W2    = (const float*)d_in[19];
    const float* b2    = (const float*)d_in[20];
    const float* gamma = (const float*)d_in[21];
    const float* beta  = (const float*)d_in[22];
    const float* Wpred = (const float*)d_in[23];
    const float* bpred = (const float*)d_in[24];
    const int*   eig   = (const int*)d_in[25];
    const int*   eilg  = (const int*)d_in[26];
    const int*   bv    = (const int*)d_in[27];
    float* out = (float*)d_out;

    cudaFuncSetAttribute(k_mgemm, cudaFuncAttributeMaxDynamicSharedMemorySize, MG_SMEM);

    // ---- weight conversion: [K,N] fp32 -> [N,K] fp16 ----
    k_wconv<<<HD / 8, 256>>>(Wmsg,           HD,  HD,  WOFF_P);
    k_wconv<<<HD / 8, 256>>>(Wmsg + HD * HD, HD,  HD,  WOFF_Q);
    for (int l = 0; l < NL; l++) {
        k_wconv<<<HD2 / 8, 256>>>(W1 + (size_t)l * HD * HD2, HD,  HD2,
                                  WOFF_W1 + (size_t)l * 131072);
        k_wconv<<<HD / 8, 256>>>(W2 + (size_t)l * HD2 * HD, HD2, HD,
                                 WOFF_W2 + (size_t)l * 131072);
    }

    // ---- setup: CSRs, basis projections, encoder ----
    int nb_lg = (EG + 1023) / 1024;   // 196
    int nb_g  = (NN + 1023) / 1024;   // 20
    k_zero_setup<<<(EG + 255) / 256, 256>>>();
    k_hist_lg<<<(ELG + 255) / 256, 256>>>(eilg);
    k_hist_g<<<(EG + 255) / 256, 256>>>(eig);
    k_hist_batch<<<(NN + 255) / 256, 256>>>(bv);
    k_scan1<<<nb_lg, 1024>>>(0);
    k_scan2<<<1, 256>>>(nb_lg);
    k_scan3<<<nb_lg, 1024>>>(0);
    k_scan1<<<nb_g, 1024>>>(1);
    k_scan2<<<1, 256>>>(nb_g);
    k_scan3<<<nb_g, 1024>>>(1);
    k_prepcur<<<(EG + 255) / 256, 256>>>();
    k_basis<<<(EG + 255) / 256, 256>>>(edb, Wgnb, bgnb, 0);
    k_basis<<<(ELG + 255) / 256, 256>>>(ealg, Wgeb, bgeb, 1);
    k_scatter_lg<<<(ELG + 255) / 256, 256>>>(eilg);
    k_scatter_g<<<(EG + 255) / 256, 256>>>(eig);
    k_enc<<<NN / 8, 256>>>(xg, Wenc, benc);

    // ---- P/Q node GEMMs + first message embedding ----
    int gpq = (NN + 127) / 128;
    k_mgemm<<<dim3(gpq, 2), 256, MG_SMEM>>>(nullptr, NN, HD, HD, 0, /*A=hn*/0, /*C=P*/0, 0, WOFF_P);
    k_mgemm<<<dim3(gpq, 2), 256, MG_SMEM>>>(nullptr, NN, HD, HD, 0, 0, /*C=Q*/1, 0, WOFF_Q);
    k_h0<<<EG / 16, 256>>>(ea, xlg, Wmsg, bmsg, eig);

    // ---- layers (BN stats fused into GEMM2 epilogue) ----
    int gE = (EG + 127) / 128;
    for (int l = 0; l < NL; l++) {
        k_agg<<<EG / AGG_NPB, 256>>>(Wlnb + l * 4 * HD, blnb + l * HD,
                                     Wleb + l * 4 * HD, bleb + l * HD, l > 0);
        k_mgemm<<<dim3(gE, 4), 256, MG_SMEM>>>(b1 + l * HD2, EG, HD2, HD, /*relu*/1,
                                               /*A=hm*/1, /*C=m2 split*/2, 0,
                                               WOFF_W1 + (size_t)l * 131072);
        k_zero_bn<<<1, 256>>>();
        k_mgemm<<<dim3(gE, 2), 256, MG_SMEM>>>(b2 + l * HD, EG, HD, HD2, /*relu*/0,
                                               /*A=m2*/2, /*C=h (stats)*/3, /*res*/(l > 0) ? 1 : 0,
                                               WOFF_W2 + (size_t)l * 131072);
        k_bncoef<<<1, 256>>>(gamma + l * HD, beta + l * HD);
    }

    // ---- scatter-to-nodes + pooling + prediction (final BN coefs from layer 3) ----
    k_pool<<<NN / 8, 256>>>(bv);
    k_pred<<<NG, 256>>>(Wpred, bpred, out);
}

// round 13
// speedup vs baseline: 1.3150x; 1.0026x over previous
#include <cuda_runtime.h>
#include <cuda_fp16.h>
#include <cstdint>

#define NN   20000
#define EG   200000
#define ELG  400000
#define HD   256
#define HD2  512
#define NL   4
#define NG   128
#define KSB  80   // padded smem row stride in BYTES (64B payload + 16 pad), ldmatrix conflict-free

// ---------------- scratch (device globals; no allocations allowed) ----------------
__device__ float  g_P[NN * HD];
__device__ float  g_Q[NN * HD];
__device__ float  g_h[EG * HD];        // current layer state (pre-BN)
__device__ float4 g_nbg[EG];
__device__ float4 g_ebg[ELG];
__device__ int    g_counts_lg[EG];
__device__ int    g_counts_g[NN];
__device__ int    g_rowptr_lg[EG + 1];
__device__ int    g_rowptr_g[NN + 1];
__device__ int    g_cursor_lg[EG];
__device__ int    g_cursor_g[NN];
__device__ int    g_src_sorted[ELG];
__device__ float4 g_nbg_sorted[ELG];
__device__ float4 g_ebg_sorted[ELG];
__device__ int    g_eid_sorted[EG];
__device__ double g_bnsum[HD];
__device__ double g_bnsq[HD];
__device__ float  g_bnscale[HD];
__device__ float  g_bnshift[HD];
__device__ float  g_gsum[NG * HD];
__device__ int    g_cnt[NG];
__device__ int    g_blksum[256];

// fp16 hi/lo A operands (padded +128 rows; device globals are zero-initialized)
__device__ __half g_hnh[(NN + 128) * HD];
__device__ __half g_hnl[(NN + 128) * HD];
__device__ __half g_hmh[(EG + 128) * HD];
__device__ __half g_hml[(EG + 128) * HD];
__device__ __half g_m2h[(EG + 128) * HD2];
__device__ __half g_m2l[(EG + 128) * HD2];

// weights single fp16, [N,K] K-contiguous
#define WOFF_P  0
#define WOFF_Q  65536
#define WOFF_W1 131072              // + l*131072
#define WOFF_W2 655360              // + l*131072
#define WTOT    1179648
__device__ __half g_Wv[WTOT];

// ---------------- mma / cp.async helpers (sm_80+ PTX, valid on sm_100 base) ----------------
__device__ __forceinline__ void ldsm4(uint32_t addr, uint32_t* r) {
    asm volatile("ldmatrix.sync.aligned.m8n8.x4.shared.b16 {%0,%1,%2,%3}, [%4];"
                 : "=r"(r[0]), "=r"(r[1]), "=r"(r[2]), "=r"(r[3]) : "r"(addr));
}
__device__ __forceinline__ void mma_f16(float* c, const uint32_t* a, uint32_t b0, uint32_t b1) {
    asm volatile("mma.sync.aligned.m16n8k16.row.col.f32.f16.f16.f32 "
                 "{%0,%1,%2,%3}, {%4,%5,%6,%7}, {%8,%9}, {%0,%1,%2,%3};"
                 : "+f"(c[0]), "+f"(c[1]), "+f"(c[2]), "+f"(c[3])
                 : "r"(a[0]), "r"(a[1]), "r"(a[2]), "r"(a[3]), "r"(b0), "r"(b1));
}
__device__ __forceinline__ uint32_t smem_u32(const void* p) {
    uint32_t a;
    asm("{ .reg .u64 t; cvta.to.shared.u64 t, %1; cvt.u32.u64 %0, t; }" : "=r"(a) : "l"(p));
    return a;
}
__device__ __forceinline__ void cpa16(uint32_t s, const void* g) {
    asm volatile("cp.async.cg.shared.global [%0], [%1], 16;" :: "r"(s), "l"(g));
}
#define CP_COMMIT() asm volatile("cp.async.commit_group;" ::: "memory")
#define CP_WAIT1()  asm volatile("cp.async.wait_group 1;" ::: "memory")

// fp16 hi/lo split
__device__ __forceinline__ void split16(float x, __half& h, __half& l) {
    h = __float2half(x);
    l = __float2half(x - __half2float(h));
}

// smem stage layout (bytes): A_hi | A_lo | B, each 128*KSB = 10240
#define SA_HI 0
#define SA_LO 10240
#define SB_V  20480
#define STG   30720
#define NSTG  3
#define MG_SMEM (NSTG * STG)

// ---------------- fp16 2-pass mma GEMM: C[M,N] = A[M,K] @ B[K,N] (+bias, relu, res) ----------
// grid: x = M-tile, y = N-tile. 2 CTAs/SM. cbuf==3 additionally accumulates BN stats (fused).
__global__ void __launch_bounds__(256, 2) k_mgemm(
    const float* __restrict__ bias,
    int M, int N, int K, int relu, int abuf, int cbuf, int addres, size_t woff)
{
    extern __shared__ char dsm[];
    const __half* Ah_ = (abuf == 0) ? g_hnh : (abuf == 1) ? g_hmh : g_m2h;
    const __half* Al_ = (abuf == 0) ? g_hnl : (abuf == 1) ? g_hml : g_m2l;
    const __half* Bv_ = g_Wv + woff;

    int tid = threadIdx.x, wid = tid >> 5, lid = tid & 31;
    int bm = blockIdx.x * 128;
    int bn = blockIdx.y * 128;
    int wm = (wid >> 2) * 64;
    int wn = (wid & 3) * 32;

    // cp.async: 4 threads/row cover 64 bytes (32 fp16); rows r0 and r0+64
    int r0 = tid >> 2, e0 = (tid & 3) * 8;       // element offset within chunk
    int r1 = r0 + 64;
    const __half* Ah0 = Ah_ + (size_t)(bm + r0) * K + e0;
    const __half* Ah1 = Ah_ + (size_t)(bm + r1) * K + e0;
    const __half* Al0 = Al_ + (size_t)(bm + r0) * K + e0;
    const __half* Al1 = Al_ + (size_t)(bm + r1) * K + e0;
    const __half* Bv0 = Bv_ + (size_t)(bn + r0) * K + e0;
    const __half* Bv1 = Bv_ + (size_t)(bn + r1) * K + e0;
    uint32_t d0 = (uint32_t)(r0 * KSB + e0 * 2);
    uint32_t d1 = (uint32_t)(r1 * KSB + e0 * 2);

    uint32_t sbase = smem_u32(dsm);

    // ldmatrix per-lane offsets (bytes)
    int a_ml = (lid & 7) + ((lid >> 3) & 1) * 8;
    int a_kb = (lid >> 4) * 16;
    int b_nl = (lid & 7) + (lid >> 4) * 8;
    int b_kb = ((lid >> 3) & 1) * 16;
    uint32_t aoff[4], boffm[2];
    #pragma unroll
    for (int mt = 0; mt < 4; mt++)
        aoff[mt] = (uint32_t)((wm + mt * 16 + a_ml) * KSB + a_kb);
    #pragma unroll
    for (int p = 0; p < 2; p++)
        boffm[p] = (uint32_t)((wn + p * 16 + b_nl) * KSB + b_kb);

    float acc[4][4][4];
    #pragma unroll
    for (int i = 0; i < 4; i++)
        #pragma unroll
        for (int j = 0; j < 4; j++)
            #pragma unroll
            for (int q = 0; q < 4; q++) acc[i][j][q] = 0.f;

    int nck = K >> 5;   // chunks of 32 fp16 (64 bytes/row)

    auto load_stage = [&](int s, int c) {
        uint32_t sb = sbase + s * STG;
        int co = c * 32;
        cpa16(sb + SA_HI + d0, Ah0 + co); cpa16(sb + SA_HI + d1, Ah1 + co);
        cpa16(sb + SA_LO + d0, Al0 + co); cpa16(sb + SA_LO + d1, Al1 + co);
        cpa16(sb + SB_V  + d0, Bv0 + co); cpa16(sb + SB_V  + d1, Bv1 + co);
    };

    load_stage(0, 0); CP_COMMIT();
    load_stage(1, 1); CP_COMMIT();

    for (int c = 0; c < nck; c++) {
        CP_WAIT1();
        __syncthreads();
        if (c + 2 < nck) load_stage((c + 2) % NSTG, c + 2);
        CP_COMMIT();
        uint32_t stb = sbase + (c % NSTG) * STG;
        #pragma unroll
        for (int kk = 0; kk < 2; kk++) {
            uint32_t ko = kk * 32;   // 32 bytes = k16 fp16 per mma
            uint32_t ah[4][4], al[4][4], bv[2][4];
            #pragma unroll
            for (int mt = 0; mt < 4; mt++) {
                ldsm4(stb + SA_HI + aoff[mt] + ko, ah[mt]);
                ldsm4(stb + SA_LO + aoff[mt] + ko, al[mt]);
            }
            #pragma unroll
            for (int p = 0; p < 2; p++)
                ldsm4(stb + SB_V + boffm[p] + ko, bv[p]);
            #pragma unroll
            for (int mt = 0; mt < 4; mt++) {
                #pragma unroll
                for (int nt = 0; nt < 4; nt++) {
                    int p = nt >> 1, o = (nt & 1) * 2;
                    mma_f16(acc[mt][nt], ah[mt], bv[p][o], bv[p][o + 1]);   // Ah*B
                    mma_f16(acc[mt][nt], al[mt], bv[p][o], bv[p][o + 1]);   // Al*B
                }
            }
        }
        __syncthreads();
    }

    // ---- epilogue ----
    int l4 = lid >> 2, lc = (lid & 3) * 2;
    float cs[8], cq[8];
    #pragma unroll
    for (int i = 0; i < 8; i++) { cs[i] = 0.f; cq[i] = 0.f; }

    #pragma unroll
    for (int mt = 0; mt < 4; mt++) {
        #pragma unroll
        for (int nt = 0; nt < 4; nt++) {
            int m = bm + wm + mt * 16 + l4;
            int n = bn + wn + nt * 8 + lc;
            float2 bia = make_float2(0.f, 0.f);
            if (bias) bia = *(const float2*)&bias[n];
            #pragma unroll
            for (int half_ = 0; half_ < 2; half_++) {
                int mm = m + half_ * 8;
                if (mm < M) {
                    float v0 = acc[mt][nt][half_ * 2 + 0] + bia.x;
                    float v1 = acc[mt][nt][half_ * 2 + 1] + bia.y;
                    if (relu) { v0 = fmaxf(v0, 0.f); v1 = fmaxf(v1, 0.f); }
                    if (cbuf == 2) {
                        // fp16 hi/lo split store to mid2
                        __half h0, l0, h1, l1;
                        split16(v0, h0, l0);
                        split16(v1, h1, l1);
                        __half2 ph; ph.x = h0; ph.y = h1;
                        __half2 pl; pl.x = l0; pl.y = l1;
                        *(__half2*)&g_m2h[(size_t)mm * N + n] = ph;
                        *(__half2*)&g_m2l[(size_t)mm * N + n] = pl;
                    } else {
                        float* C = (cbuf == 0) ? g_P : (cbuf == 1) ? g_Q : g_h;
                        if (addres) {
                            float2 rr = *(const float2*)&g_h[(size_t)mm * N + n];
                            v0 += rr.x; v1 += rr.y;
                        }
                        float2 ov; ov.x = v0; ov.y = v1;
                        *(float2*)&C[(size_t)mm * N + n] = ov;
                        if (cbuf == 3) {
                            cs[nt * 2 + 0] += v0; cq[nt * 2 + 0] += v0 * v0;
                            cs[nt * 2 + 1] += v1; cq[nt * 2 + 1] += v1 * v1;
                        }
                    }
                }
            }
        }
    }

    // ---- fused BN stats reduction (cbuf==3 only) ----
    if (cbuf == 3) {
        #pragma unroll
        for (int i = 0; i < 8; i++) {
            #pragma unroll
            for (int o = 4; o < 32; o <<= 1) {
                cs[i] += __shfl_down_sync(0xFFFFFFFF, cs[i], o);
                cq[i] += __shfl_down_sync(0xFFFFFFFF, cq[i], o);
            }
        }
        float* s_sum = (float*)dsm;             // 128 floats
        float* s_sq  = (float*)(dsm + 512);     // 128 floats
        if (tid < 128) { s_sum[tid] = 0.f; s_sq[tid] = 0.f; }
        __syncthreads();
        if (lid < 4) {
            #pragma unroll
            for (int nt = 0; nt < 4; nt++) {
                int col = wn + nt * 8 + lid * 2;   // local 0..127
                atomicAdd(&s_sum[col],     cs[nt * 2 + 0]);
                atomicAdd(&s_sq[col],      cq[nt * 2 + 0]);
                atomicAdd(&s_sum[col + 1], cs[nt * 2 + 1]);
                atomicAdd(&s_sq[col + 1],  cq[nt * 2 + 1]);
            }
        }
        __syncthreads();
        if (tid < 128) {
            atomicAdd(&g_bnsum[bn + tid], (double)s_sum[tid]);
            atomicAdd(&g_bnsq[bn + tid],  (double)s_sq[tid]);
        }
    }
}

// ---------------- merged weight convert: all matrices -> g_Wv [N,K] fp16 ----------------
// global warp id g maps: [0,256) P | [256,512) Q | [512,2560) W1 | [2560,3584) W2
__global__ void k_wconv_all(const float* __restrict__ Wmsg,
                            const float* __restrict__ W1,
                            const float* __restrict__ W2) {
    int g = blockIdx.x * 8 + (threadIdx.x >> 5);
    int lane = threadIdx.x & 31;
    const float* in;
    int K, N, n;
    size_t woff;
    if (g < 256)        { in = Wmsg;                               K = HD;  N = HD;  n = g;                woff = WOFF_P; }
    else if (g < 512)   { in = Wmsg + HD * HD;                     K = HD;  N = HD;  n = g - 256;          woff = WOFF_Q; }
    else if (g < 2560)  { int l = (g - 512) >> 9;
                          in = W1 + (size_t)l * HD * HD2;          K = HD;  N = HD2; n = (g - 512) & 511;  woff = WOFF_W1 + (size_t)l * 131072; }
    else                { int l = (g - 2560) >> 8;
                          in = W2 + (size_t)l * HD2 * HD;          K = HD2; N = HD;  n = (g - 2560) & 255; woff = WOFF_W2 + (size_t)l * 131072; }
    for (int k = lane; k < K; k += 32)
        g_Wv[woff + (size_t)n * K + k] = __float2half(in[(size_t)k * N + n]);
}

// ---------------- setup / zero (incl. BN accumulators) ----------------
__global__ void k_zero_setup() {
    int i = blockIdx.x * 256 + threadIdx.x;
    if (i < EG)       g_counts_lg[i] = 0;
    if (i < NN)       g_counts_g[i] = 0;
    if (i < NG * HD)  g_gsum[i] = 0.f;
    if (i < NG)       g_cnt[i] = 0;
    if (i < HD)       { g_bnsum[i] = 0.0; g_bnsq[i] = 0.0; }
}

// ---------------- merged histograms ----------------
__global__ void k_hist(const int* __restrict__ eilg, const int* __restrict__ eig,
                       const int* __restrict__ bv) {
    int i = blockIdx.x * 256 + threadIdx.x;
    if (i < ELG) atomicAdd(&g_counts_lg[eilg[ELG + i]], 1);
    if (i < EG)  atomicAdd(&g_counts_g[eig[EG + i]], 1);
    if (i < NN)  atomicAdd(&g_cnt[bv[i]], 1);
}

// ---------------- parallel 3-phase exclusive scan ----------------
__global__ void k_scan1(int which) {
    const int* in = (which == 0) ? g_counts_lg : g_counts_g;
    int n = (which == 0) ? EG : NN;
    int b = blockIdx.x, t = threadIdx.x, lane = t & 31, w = t >> 5;
    __shared__ int ws[32];
    int i = b * 1024 + t;
    int v = (i < n) ? in[i] : 0;
    #pragma unroll
    for (int o = 16; o > 0; o >>= 1) v += __shfl_xor_sync(0xFFFFFFFF, v, o);
    if (lane == 0) ws[w] = v;
    __syncthreads();
    if (t == 0) {
        int s = 0;
        #pragma unroll
        for (int k = 0; k < 32; k++) s += ws[k];
        g_blksum[b] = s;
    }
}
__global__ void k_scan2(int nb) {
    __shared__ int ws[8];
    int t = threadIdx.x, lane = t & 31, w = t >> 5;
    int v = (t < nb) ? g_blksum[t] : 0;
    int x = v;
    #pragma unroll
    for (int o = 1; o < 32; o <<= 1) {
        int y = __shfl_up_sync(0xFFFFFFFF, x, o);
        if (lane >= o) x += y;
    }
    if (lane == 31) ws[w] = x;
    __syncthreads();
    if (w == 0 && lane < 8) {
        int s = ws[lane];
        #pragma unroll
        for (int o = 1; o < 8; o <<= 1) {
            int y = __shfl_up_sync(0xFF, s, o);
            if (lane >= o) s += y;
        }
        ws[lane] = s;
    }
    __syncthreads();
    int woff = (w > 0) ? ws[w - 1] : 0;
    if (t < nb) g_blksum[t] = woff + x - v;   // exclusive
}
// phase 3: block-local exclusive scan + block offset; also writes cursor copy
__global__ void k_scan3(int which) {
    const int* in;
    int* out;
    int* cur;
    int n;
    if (which == 0) { in = g_counts_lg; out = g_rowptr_lg; cur = g_cursor_lg; n = EG; }
    else            { in = g_counts_g;  out = g_rowptr_g;  cur = g_cursor_g;  n = NN; }
    __shared__ int ws[32];
    int b = blockIdx.x, t = threadIdx.x, lane = t & 31, w = t >> 5;
    int i = b * 1024 + t;
    int v = (i < n) ? in[i] : 0;
    int x = v;
    #pragma unroll
    for (int o = 1; o < 32; o <<= 1) {
        int y = __shfl_up_sync(0xFFFFFFFF, x, o);
        if (lane >= o) x += y;
    }
    if (lane == 31) ws[w] = x;
    __syncthreads();
    if (w == 0) {
        int s = ws[lane];
        #pragma unroll
        for (int o = 1; o < 32; o <<= 1) {
            int y = __shfl_up_sync(0xFFFFFFFF, s, o);
            if (lane >= o) s += y;
        }
        ws[lane] = s;
    }
    __syncthreads();
    int woff = (w > 0) ? ws[w - 1] : 0;
    int base = g_blksum[b];
    if (i < n) {
        int e = base + woff + x - v;
        out[i] = e;
        cur[i] = e;
    }
    if (i == n - 1) out[n] = base + woff + x;   // total
}

// ---------------- merged tiny 4->4 basis projections ----------------
__global__ void k_basis(const float* __restrict__ edb, const float* __restrict__ Wnb,
                        const float* __restrict__ bnb, const float* __restrict__ ealg,
                        const float* __restrict__ Web, const float* __restrict__ beb) {
    int r = blockIdx.x * 256 + threadIdx.x;
    if (r < EG) {
        float4 v = ((const float4*)edb)[r];
        float4 o;
        o.x = v.x * Wnb[0] + v.y * Wnb[4] + v.z * Wnb[8]  + v.w * Wnb[12] + bnb[0];
        o.y = v.x * Wnb[1] + v.y * Wnb[5] + v.z * Wnb[9]  + v.w * Wnb[13] + bnb[1];
        o.z = v.x * Wnb[2] + v.y * Wnb[6] + v.z * Wnb[10] + v.w * Wnb[14] + bnb[2];
        o.w = v.x * Wnb[3] + v.y * Wnb[7] + v.z * Wnb[11] + v.w * Wnb[15] + bnb[3];
        g_nbg[r] = o;
    }
    if (r < ELG) {
        float4 v = ((const float4*)ealg)[r];
        float4 o;
        o.x = v.x * Web[0] + v.y * Web[4] + v.z * Web[8]  + v.w * Web[12] + beb[0];
        o.y = v.x * Web[1] + v.y * Web[5] + v.z * Web[9]  + v.w * Web[13] + beb[1];
        o.z = v.x * Web[2] + v.y * Web[6] + v.z * Web[10] + v.w * Web[14] + beb[2];
        o.w = v.x * Web[3] + v.y * Web[7] + v.z * Web[11] + v.w * Web[15] + beb[3];
        g_ebg[r] = o;
    }
}

// ---------------- merged scatter (counting-sort finish) ----------------
__global__ void k_scatter(const int* __restrict__ eilg, const int* __restrict__ eig) {
    int e = blockIdx.x * 256 + threadIdx.x;
    if (e < ELG) {
        int s = eilg[e];
        int d = eilg[ELG + e];
        int pos = atomicAdd(&g_cursor_lg[d], 1);
        g_src_sorted[pos] = s;
        g_nbg_sorted[pos] = g_nbg[s];
        g_ebg_sorted[pos] = g_ebg[e];
    }
    if (e < EG) {
        int d = eig[EG + e];
        int pos = atomicAdd(&g_cursor_g[d], 1);
        g_eid_sorted[pos] = e;
    }
}

// ---------------- node encoder: h_node = x_g @ W_enc + b_enc (fp16 hi/lo out) ----------------
__global__ void __launch_bounds__(256) k_enc(const float* __restrict__ xg,
                                             const float* __restrict__ Wenc,
                                             const float* __restrict__ benc) {
    __shared__ float xs[8][16];
    int t = threadIdx.x;
    int r0 = blockIdx.x * 8;
    if (t < 128) xs[t >> 4][t & 15] = xg[(r0 + (t >> 4)) * 16 + (t & 15)];
    __syncthreads();
    int f = t;
    float w[16];
    #pragma unroll
    for (int k = 0; k < 16; k++) w[k] = Wenc[k * HD + f];
    float b = benc[f];
    #pragma unroll
    for (int rr = 0; rr < 8; rr++) {
        float acc = b;
        #pragma unroll
        for (int k = 0; k < 16; k++) acc += xs[rr][k] * w[k];
        size_t idx = (size_t)(r0 + rr) * HD + f;
        __half h, l;
        split16(acc, h, l);
        g_hnh[idx] = h;
        g_hnl[idx] = l;
    }
}

// ---------------- first message embedding ----------------
__global__ void __launch_bounds__(256) k_h0(const float* __restrict__ ea,
                                            const float* __restrict__ xlg,
                                            const float* __restrict__ Wmsg,
                                            const float* __restrict__ bmsg,
                                            const int* __restrict__ eig) {
    __shared__ float sea[16][16];
    __shared__ float sxl[16][4];
    __shared__ int ssrc[16], sdst[16];
    int t = threadIdx.x;
    int e0 = blockIdx.x * 16;
    sea[t >> 4][t & 15] = ea[(size_t)e0 * 16 + t];
    if (t < 64) sxl[t >> 2][t & 3] = xlg[(size_t)e0 * 4 + t];
    if (t < 16) { ssrc[t] = eig[e0 + t]; sdst[t] = eig[EG + e0 + t]; }
    __syncthreads();
    int f = t;
    float wme[16];
    #pragma unroll
    for (int k = 0; k < 16; k++) wme[k] = Wmsg[(size_t)(512 + k) * HD + f];
    float wmx[4];
    #pragma unroll
    for (int k = 0; k < 4; k++) wmx[k] = Wmsg[(size_t)(528 + k) * HD + f];
    float bb = bmsg[f];
    #pragma unroll 1
    for (int ee = 0; ee < 16; ee++) {
        int e = e0 + ee;
        int s = ssrc[ee], d = sdst[ee];
        float acc = g_P[(size_t)s * HD + f] + g_Q[(size_t)d * HD + f] + bb;
        #pragma unroll
        for (int k = 0; k < 16; k++) acc += sea[ee][k] * wme[k];
        #pragma unroll
        for (int k = 0; k < 4; k++) acc += sxl[ee][k] * wmx[k];
        g_h[(size_t)e * HD + f] = acc;
    }
}

// ---------------- GENConv aggregation (online softmax, BN folded, fp16 hi/lo out) -------------
#define AGG_NPB 4
__global__ void __launch_bounds__(256) k_agg(const float* __restrict__ Wnb,
                                             const float* __restrict__ bnb,
                                             const float* __restrict__ Web,
                                             const float* __restrict__ beb,
                                             int use_bn) {
    int f = threadIdx.x;
    float w0 = Wnb[f], w1 = Wnb[HD + f], w2 = Wnb[2 * HD + f], w3 = Wnb[3 * HD + f];
    float e0 = Web[f], e1 = Web[HD + f], e2 = Web[2 * HD + f], e3 = Web[3 * HD + f];
    float cb = bnb[f] + beb[f];
    float sc = use_bn ? g_bnscale[f] : 1.f;
    float shv = use_bn ? g_bnshift[f] : 0.f;
    int d0 = blockIdx.x * AGG_NPB;
    const float NEG_INF = __int_as_float(0xff800000);
    #pragma unroll 1
    for (int dd = 0; dd < AGG_NPB; dd++) {
        int d = d0 + dd;
        int beg = g_rowptr_lg[d], end = g_rowptr_lg[d + 1];
        float xc = g_h[(size_t)d * HD + f];
        if (use_bn) xc = fmaxf(xc * sc + shv, 0.f);
        float M = NEG_INF, s = 0.f, w = 0.f;
        for (int p = beg; p < end; p++) {
            int srcn = g_src_sorted[p];
            float4 nb = g_nbg_sorted[p];
            float4 eb = g_ebg_sorted[p];
            float xv = g_h[(size_t)srcn * HD + f];
            if (use_bn) xv = fmaxf(xv * sc + shv, 0.f);
            float m = xv + nb.x * w0 + nb.y * w1 + nb.z * w2 + nb.w * w3
                         + eb.x * e0 + eb.y * e1 + eb.z * e2 + eb.w * e3 + cb;
            m = fmaxf(m, 0.f) + 1e-7f;
            float nM = fmaxf(M, m);
            float corr = __expf(M - nM);
            float ev = __expf(m - nM);
            s = s * corr + ev;
            w = w * corr + ev * m;
            M = nM;
        }
        float aggr = (end > beg) ? w / (s + 1e-16f) : 0.f;
        float val = xc + aggr;
        size_t idx = (size_t)d * HD + f;
        __half h, l;
        split16(val, h, l);
        g_hmh[idx] = h;
        g_hml[idx] = l;
    }
}

// ---------------- BN coefficients (reads accumulators, then self-zeroes them) ----------------
__global__ void k_bncoef(const float* __restrict__ gamma, const float* __restrict__ beta) {
    int f = threadIdx.x;
    double sum = g_bnsum[f];
    double sq  = g_bnsq[f];
    g_bnsum[f] = 0.0;          // ready for next layer's fused accumulation
    g_bnsq[f]  = 0.0;
    double mean = sum / (double)EG;
    double var = sq / (double)EG - mean * mean;
    double r = 1.0 / sqrt(var + 1e-5);
    float scl = (float)((double)gamma[f] * r);
    g_bnscale[f] = scl;
    g_bnshift[f] = (float)((double)beta[f] - mean * (double)scl);
}

// ---------------- final: scatter to nodes (with final BN) + graph pooling ----------------
__global__ void __launch_bounds__(256) k_pool(const int* __restrict__ bv) {
    int f = threadIdx.x;
    float sc = g_bnscale[f], sh = g_bnshift[f];
    int n0 = blockIdx.x * 8;
    #pragma unroll 1
    for (int nn = 0; nn < 8; nn++) {
        int n = n0 + nn;
        int beg = g_rowptr_g[n], end = g_rowptr_g[n + 1];
        if (end > beg) {
            float acc = 0.f;
            for (int p = beg; p < end; p++) {
                int e = g_eid_sorted[p];
                acc += g_h[(size_t)e * HD + f] * sc + sh;
            }
            atomicAdd(&g_gsum[(size_t)bv[n] * HD + f], acc);
        }
    }
}

__global__ void k_pred(const float* __restrict__ Wpred, const float* __restrict__ bpred,
                       float* __restrict__ out) {
    __shared__ float red[256];
    int g = blockIdx.x;
    int f = threadIdx.x;
    float c = fmaxf((float)g_cnt[g], 1.0f);
    float v = (g_gsum[(size_t)g * HD + f] / c) * Wpred[f];
    red[f] = v;
    __syncthreads();
    for (int stw = 128; stw > 0; stw >>= 1) {
        if (f < stw) red[f] += red[f + stw];
        __syncthreads();
    }
    if (f == 0) out[g] = red[0] + bpred[0];
}

// ---------------- host ----------------
extern "C" void kernel_launch(void* const* d_in, const int* in_sizes, int n_in,
                              void* d_out, int out_size) {
    const float* xg    = (const float*)d_in[0];
    const float* ea    = (const float*)d_in[1];
    const float* xlg   = (const float*)d_in[2];
    const float* edb   = (const float*)d_in[3];
    const float* ealg  = (const float*)d_in[4];
    const float* Wenc  = (const float*)d_in[5];
    const float* benc  = (const float*)d_in[6];
    const float* Wmsg  = (const float*)d_in[7];
    const float* bmsg  = (const float*)d_in[8];
    const float* Wgnb  = (const float*)d_in[9];
    const float* bgnb  = (const float*)d_in[10];
    const float* Wgeb  = (const float*)d_in[11];
    const float* bgeb  = (const float*)d_in[12];
    const float* Wlnb  = (const float*)d_in[13];
    const float* blnb  = (const float*)d_in[14];
    const float* Wleb  = (const float*)d_in[15];
    const float* bleb  = (const float*)d_in[16];
    const float* W1    = (const float*)d_in[17];
    const float* b1    = (const float*)d_in[18];
    const float* W2    = (const float*)d_in[19];
    const float* b2    = (const float*)d_in[20];
    const float* gamma = (const float*)d_in[21];
    const float* beta  = (const float*)d_in[22];
    const float* Wpred = (const float*)d_in[23];
    const float* bpred = (const float*)d_in[24];
    const int*   eig   = (const int*)d_in[25];
    const int*   eilg  = (const int*)d_in[26];
    const int*   bv    = (const int*)d_in[27];
    float* out = (float*)d_out;

    cudaFuncSetAttribute(k_mgemm, cudaFuncAttributeMaxDynamicSharedMemorySize, MG_SMEM);

    // ---- weight conversion: all matrices, single launch ----
    k_wconv_all<<<448, 256>>>(Wmsg, W1, W2);

    // ---- setup: CSRs, basis projections, encoder ----
    int nb_lg = (EG + 1023) / 1024;   // 196
    int nb_g  = (NN + 1023) / 1024;   // 20
    k_zero_setup<<<(EG + 255) / 256, 256>>>();
    k_hist<<<(ELG + 255) / 256, 256>>>(eilg, eig, bv);
    k_scan1<<<nb_lg, 1024>>>(0);
    k_scan2<<<1, 256>>>(nb_lg);
    k_scan3<<<nb_lg, 1024>>>(0);
    k_scan1<<<nb_g, 1024>>>(1);
    k_scan2<<<1, 256>>>(nb_g);
    k_scan3<<<nb_g, 1024>>>(1);
    k_basis<<<(ELG + 255) / 256, 256>>>(edb, Wgnb, bgnb, ealg, Wgeb, bgeb);
    k_scatter<<<(ELG + 255) / 256, 256>>>(eilg, eig);
    k_enc<<<NN / 8, 256>>>(xg, Wenc, benc);

    // ---- P/Q node GEMMs + first message embedding ----
    int gpq = (NN + 127) / 128;
    k_mgemm<<<dim3(gpq, 2), 256, MG_SMEM>>>(nullptr, NN, HD, HD, 0, /*A=hn*/0, /*C=P*/0, 0, WOFF_P);
    k_mgemm<<<dim3(gpq, 2), 256, MG_SMEM>>>(nullptr, NN, HD, HD, 0, 0, /*C=Q*/1, 0, WOFF_Q);
    k_h0<<<EG / 16, 256>>>(ea, xlg, Wmsg, bmsg, eig);

    // ---- layers (BN stats fused into GEMM2 epilogue; bncoef self-zeroes) ----
    int gE = (EG + 127) / 128;
    for (int l = 0; l < NL; l++) {
        k_agg<<<EG / AGG_NPB, 256>>>(Wlnb + l * 4 * HD, blnb + l * HD,
                                     Wleb + l * 4 * HD, bleb + l * HD, l > 0);
        k_mgemm<<<dim3(gE, 4), 256, MG_SMEM>>>(b1 + l * HD2, EG, HD2, HD, /*relu*/1,
                                               /*A=hm*/1, /*C=m2 split*/2, 0,
                                               WOFF_W1 + (size_t)l * 131072);
        k_mgemm<<<dim3(gE, 2), 256, MG_SMEM>>>(b2 + l * HD, EG, HD, HD2, /*relu*/0,
                                               /*A=m2*/2, /*C=h (stats)*/3, /*res*/(l > 0) ? 1 : 0,
                                               WOFF_W2 + (size_t)l * 131072);
        k_bncoef<<<1, 256>>>(gamma + l * HD, beta + l * HD);
    }

    // ---- scatter-to-nodes + pooling + prediction (final BN coefs from layer 3) ----
    k_pool<<<NN / 8, 256>>>(bv);
    k_pred<<<NG, 256>>>(Wpred, bpred, out);
}